// round 12
// baseline (speedup 1.0000x reference)
#include <cuda_runtime.h>
#include <cuda_bf16.h>
#include <cstdint>
#include <math.h>

// ---------------------------------------------------------------------------
// SiglipAttention: B=8, N=1024, D=1152, H=16, Hd=72
// Outputs (concatenated in d_out): out [B,N,D] fp32, attn_probs [B,H,N,N] fp32
// ---------------------------------------------------------------------------

#define BD   8
#define SEQ  1024
#define DIM  1152
#define NH   16
#define HD   72
#define MTOT (BD * SEQ)                 // 8192
#define OUT_ELEMS (BD * SEQ * DIM)      // 9437184
#define WELEMS (DIM * DIM)              // 1327104
#define SCALE_F 0.117851130197757931f   // 72^-0.5

// Scratch (allocation-free rule: __device__ globals).  All MMA operands are
// PRE-SPLIT hi/lo bf16.  Q/K/V/ctx all live in [B,N,D] row layout (head h at
// columns h*72..h*72+71) so every epilogue store is contiguous.
__device__ __nv_bfloat16 g_xh[OUT_ELEMS],  g_xl[OUT_ELEMS];    // x
__device__ __nv_bfloat16 g_wh[4][WELEMS],  g_wl[4][WELEMS];    // q,k,v,o weights
__device__ __nv_bfloat16 g_qh[OUT_ELEMS],  g_ql[OUT_ELEMS];    // Q
__device__ __nv_bfloat16 g_kh[OUT_ELEMS],  g_kl[OUT_ELEMS];    // K
__device__ __nv_bfloat16 g_vh[OUT_ELEMS],  g_vl[OUT_ELEMS];    // V
__device__ __nv_bfloat16 g_ch[OUT_ELEMS],  g_cl[OUT_ELEMS];    // ctx

// ===========================================================================
// HMMA + cp.async helpers (sm_80+ paths; tcgen05 unavailable on sm_103 base)
// ===========================================================================
__device__ __forceinline__ uint32_t smem_u32(const void* p) {
    uint32_t a;
    asm("{ .reg .u64 t; cvta.to.shared.u64 t, %1; cvt.u32.u64 %0, t; }"
        : "=r"(a) : "l"(p));
    return a;
}
__device__ __forceinline__ void ldsm_x4(uint32_t& r0, uint32_t& r1,
                                        uint32_t& r2, uint32_t& r3, uint32_t a) {
    asm volatile("ldmatrix.sync.aligned.m8n8.x4.shared.b16 {%0,%1,%2,%3}, [%4];"
                 : "=r"(r0), "=r"(r1), "=r"(r2), "=r"(r3) : "r"(a));
}
__device__ __forceinline__ void ldsm_x2(uint32_t& r0, uint32_t& r1, uint32_t a) {
    asm volatile("ldmatrix.sync.aligned.m8n8.x2.shared.b16 {%0,%1}, [%2];"
                 : "=r"(r0), "=r"(r1) : "r"(a));
}
__device__ __forceinline__ void mma16816(float* c,
                                         uint32_t a0, uint32_t a1, uint32_t a2, uint32_t a3,
                                         uint32_t b0, uint32_t b1) {
    asm volatile(
        "mma.sync.aligned.m16n8k16.row.col.f32.bf16.bf16.f32 "
        "{%0,%1,%2,%3}, {%4,%5,%6,%7}, {%8,%9}, {%0,%1,%2,%3};"
        : "+f"(c[0]), "+f"(c[1]), "+f"(c[2]), "+f"(c[3])
        : "r"(a0), "r"(a1), "r"(a2), "r"(a3), "r"(b0), "r"(b1));
}
__device__ __forceinline__ void cp16(uint32_t s, const void* g) {
    asm volatile("cp.async.ca.shared.global [%0], [%1], 16;"
                 :: "r"(s), "l"(__cvta_generic_to_global(g)));
}
__device__ __forceinline__ void cp_commit() {
    asm volatile("cp.async.commit_group;");
}
template <int N>
__device__ __forceinline__ void cp_wait() {
    asm volatile("cp.async.wait_group %0;" :: "n"(N));
}

// split fp32x4 -> hi bf16x4 + lo bf16x4 (packed as uint2 each)
__device__ __forceinline__ void split8(uint2& hi, uint2& lo, float4 v) {
    __nv_bfloat162 h01 = __floats2bfloat162_rn(v.x, v.y);
    __nv_bfloat162 h23 = __floats2bfloat162_rn(v.z, v.w);
    float rx = v.x - __bfloat162float(h01.x);
    float ry = v.y - __bfloat162float(h01.y);
    float rz = v.z - __bfloat162float(h23.x);
    float rw = v.w - __bfloat162float(h23.y);
    hi = make_uint2(*(uint32_t*)&h01, *(uint32_t*)&h23);
    __nv_bfloat162 l01 = __floats2bfloat162_rn(rx, ry);
    __nv_bfloat162 l23 = __floats2bfloat162_rn(rz, rw);
    lo = make_uint2(*(uint32_t*)&l01, *(uint32_t*)&l23);
}
__device__ __forceinline__ void split2(uint32_t& hi, uint32_t& lo, float x, float y) {
    __nv_bfloat162 h = __floats2bfloat162_rn(x, y);
    float rx = x - __bfloat162float(h.x);
    float ry = y - __bfloat162float(h.y);
    hi = *(uint32_t*)&h;
    __nv_bfloat162 l = __floats2bfloat162_rn(rx, ry);
    lo = *(uint32_t*)&l;
}

// ===========================================================================
// Kernel 0: pre-split x and the 4 weight matrices (once).
// ===========================================================================
#define X_F4   (OUT_ELEMS / 4)
#define W_F4   (WELEMS / 4)
#define PREP_TOTAL (X_F4 + 4 * W_F4)

__global__ __launch_bounds__(256) void prep_kernel(
    const float* __restrict__ x,
    const float* __restrict__ qw, const float* __restrict__ kw,
    const float* __restrict__ vw, const float* __restrict__ ow)
{
    const size_t i = (size_t)blockIdx.x * 256 + threadIdx.x;
    if (i >= PREP_TOTAL) return;
    const float* src;
    __nv_bfloat16 *dh, *dl;
    size_t e;
    if (i < X_F4) {
        src = x; dh = g_xh; dl = g_xl; e = i;
    } else {
        const size_t wi = i - X_F4;
        const int wsel = (int)(wi / W_F4);
        e = wi % W_F4;
        src = (wsel == 0) ? qw : (wsel == 1) ? kw : (wsel == 2) ? vw : ow;
        dh = g_wh[wsel]; dl = g_wl[wsel];
    }
    float4 v = *(const float4*)(src + e * 4);
    uint2 h, l;
    split8(h, l, v);
    *(uint2*)(dh + e * 4) = h;
    *(uint2*)(dl + e * 4) = l;
}

// ===========================================================================
// Common bf16x3 HMMA GEMM core, cp.async 2-stage pipelined.
//   y[128,128] = A[M,K] @ W[N,K]^T ; 36 K-chunks of 32.
// MODE 0: epilogue -> hi/lo bf16 [M,DIM] (qkv) ; MODE 1: fp32 [M,DIM] (o-proj)
// ===========================================================================
#define TSTR 40                           // bf16 per smem row (80B, conflict-free)
#define GT_ARR (128 * TSTR)               // 5120 elems per array
#define GT_STAGE (4 * GT_ARR)             // elems per stage (Ah,Al,Bh,Bl)
#define GT_SMEM_BYTES (2 * GT_STAGE * 2)  // 81920

template <int MODE>
__device__ __forceinline__ void tc_gemm_tile(
    const __nv_bfloat16* __restrict__ Agh, const __nv_bfloat16* __restrict__ Agl,
    const __nv_bfloat16* __restrict__ Wgh, const __nv_bfloat16* __restrict__ Wgl,
    const float* __restrict__ bias,
    float* __restrict__ dst, __nv_bfloat16* __restrict__ dsth,
    __nv_bfloat16* __restrict__ dstl,
    int m0, int n0)
{
    extern __shared__ __nv_bfloat16 gsm[];
    const int tid  = threadIdx.x;
    const int lane = tid & 31;
    const int wid  = tid >> 5;
    const int wm   = (wid >> 2) * 64;
    const int wn   = (wid & 3) * 32;
    const uint32_t sbase = smem_u32(gsm);

    auto issue = [&](int c, int s) {
        const uint32_t st = sbase + (uint32_t)s * (GT_STAGE * 2);
#pragma unroll
        for (int t = 0; t < 2; t++) {
            const int idx = tid + t * 256;           // 0..511
            const int row = idx >> 2;
            const int c8  = (idx & 3) * 8;
            const size_t ga = (size_t)(m0 + row) * DIM + c * 32 + c8;
            const size_t gb = (size_t)(n0 + row) * DIM + c * 32 + c8;
            const uint32_t so = (uint32_t)(row * TSTR + c8) * 2;
            cp16(st + 0 * GT_ARR * 2 + so, Agh + ga);
            cp16(st + 1 * GT_ARR * 2 + so, Agl + ga);
            cp16(st + 2 * GT_ARR * 2 + so, Wgh + gb);
            cp16(st + 3 * GT_ARR * 2 + so, Wgl + gb);
        }
        cp_commit();
    };

    float acc[4][4][4];
#pragma unroll
    for (int i = 0; i < 4; i++)
#pragma unroll
        for (int j = 0; j < 4; j++)
#pragma unroll
            for (int q = 0; q < 4; q++) acc[i][j][q] = 0.f;

    const uint32_t a_off = (wm + (lane & 15)) * (TSTR * 2) + (lane >> 4) * 16;
    const uint32_t b_row_base = wn + (lane & 7);
    const uint32_t b_off = ((lane >> 3) & 1) * 16;

    issue(0, 0);
    issue(1, 1);

    for (int c = 0; c < 36; c++) {
        const int s = c & 1;
        if (c + 1 < 36) cp_wait<1>(); else cp_wait<0>();
        __syncthreads();

        const uint32_t st = sbase + (uint32_t)s * (GT_STAGE * 2);
        const uint32_t ah = st, al = st + GT_ARR * 2;
        const uint32_t bh = st + 2 * GT_ARR * 2, bl = st + 3 * GT_ARR * 2;

#pragma unroll
        for (int ks = 0; ks < 2; ks++) {
            uint32_t Ah[4][4], Al[4][4], Bh[4][2], Bl[4][2];
#pragma unroll
            for (int mf = 0; mf < 4; mf++) {
                const uint32_t addr = a_off + mf * 16 * (TSTR * 2) + ks * 32;
                ldsm_x4(Ah[mf][0], Ah[mf][1], Ah[mf][2], Ah[mf][3], ah + addr);
                ldsm_x4(Al[mf][0], Al[mf][1], Al[mf][2], Al[mf][3], al + addr);
            }
#pragma unroll
            for (int nf = 0; nf < 4; nf++) {
                const uint32_t addr = (b_row_base + nf * 8) * (TSTR * 2) + ks * 32 + b_off;
                ldsm_x2(Bh[nf][0], Bh[nf][1], bh + addr);
                ldsm_x2(Bl[nf][0], Bl[nf][1], bl + addr);
            }
#pragma unroll
            for (int mf = 0; mf < 4; mf++)
#pragma unroll
                for (int nf = 0; nf < 4; nf++) {
                    mma16816(acc[mf][nf], Ah[mf][0], Ah[mf][1], Ah[mf][2], Ah[mf][3],
                             Bh[nf][0], Bh[nf][1]);
                    mma16816(acc[mf][nf], Al[mf][0], Al[mf][1], Al[mf][2], Al[mf][3],
                             Bh[nf][0], Bh[nf][1]);
                    mma16816(acc[mf][nf], Ah[mf][0], Ah[mf][1], Ah[mf][2], Ah[mf][3],
                             Bl[nf][0], Bl[nf][1]);
                }
        }
        __syncthreads();
        if (c + 2 < 36) issue(c + 2, s);
    }

    const int r_base = m0 + wm + (lane >> 2);
    const int c_base = n0 + wn + (lane & 3) * 2;
#pragma unroll
    for (int mf = 0; mf < 4; mf++) {
#pragma unroll
        for (int nf = 0; nf < 4; nf++) {
            const int col = c_base + nf * 8;
            const float bx = bias[col], by = bias[col + 1];
#pragma unroll
            for (int half = 0; half < 2; half++) {
                const int row = r_base + mf * 16 + half * 8;
                const float vx = acc[mf][nf][half * 2 + 0] + bx;
                const float vy = acc[mf][nf][half * 2 + 1] + by;
                const size_t ga = (size_t)row * DIM + col;
                if (MODE == 0) {
                    uint32_t hi, lo;
                    split2(hi, lo, vx, vy);
                    *(uint32_t*)(dsth + ga) = hi;
                    *(uint32_t*)(dstl + ga) = lo;
                } else {
                    float2 v; v.x = vx; v.y = vy;
                    *(float2*)(dst + ga) = v;
                }
            }
        }
    }
}

// Kernel 1: QKV projection -> pre-split bf16 [B,N,D]
__global__ __launch_bounds__(256) void qkv_tc_kernel(
    const float* __restrict__ qb, const float* __restrict__ kb,
    const float* __restrict__ vb)
{
    const int proj = blockIdx.z;
    const float* bias = (proj == 0) ? qb : (proj == 1) ? kb : vb;
    __nv_bfloat16* dh = (proj == 0) ? g_qh : (proj == 1) ? g_kh : g_vh;
    __nv_bfloat16* dl = (proj == 0) ? g_ql : (proj == 1) ? g_kl : g_vl;
    tc_gemm_tile<0>(g_xh, g_xl, g_wh[proj], g_wl[proj], bias,
                    nullptr, dh, dl, blockIdx.y * 128, blockIdx.x * 128);
}

// Kernel 5: O projection -> fp32 out
__global__ __launch_bounds__(256) void oproj_tc_kernel(
    const float* __restrict__ ob, float* __restrict__ out)
{
    tc_gemm_tile<1>(g_ch, g_cl, g_wh[3], g_wl[3], ob,
                    out, nullptr, nullptr, blockIdx.y * 128, blockIdx.x * 128);
}

// ===========================================================================
// Kernel 2: FUSED scores + softmax, register-resident S.
//   16 q-rows x 1024 keys per CTA.  All warps hold fragments of the SAME 16
//   rows (columns split across warps) -> row sums need quad-reduce THEN a
//   cross-warp smem reduction (the R8 bug was omitting the latter).
//   Softmax has no max pass: shift-invariance is exact and scores are
//   bounded (~N(0,2), max << exp overflow).
// ===========================================================================
#define FS_KSTR 88
#define FS_TILE (128 * FS_KSTR)          // elems per array
#define FS_SMEM (4 * FS_TILE * 2)        // 2 stages x (hi+lo) = 90112 bytes

__global__ __launch_bounds__(256, 2) void fused_scores_softmax_kernel(
    float* __restrict__ probs)
{
    extern __shared__ __nv_bfloat16 ksm[];
    __shared__ float srow[8][16];        // [warp][row] partial row sums
    const int tid  = threadIdx.x;
    const int lane = tid & 31;
    const int w    = tid >> 5;
    const int q0   = blockIdx.x * 16;
    const int bhx  = blockIdx.y;
    const int bb   = bhx >> 4, hh = bhx & 15;

    const __nv_bfloat16* Qgh = g_qh + ((size_t)(bb * SEQ + q0)) * DIM + hh * HD;
    const __nv_bfloat16* Qgl = g_ql + ((size_t)(bb * SEQ + q0)) * DIM + hh * HD;
    const __nv_bfloat16* Kgh = g_kh + ((size_t)(bb * SEQ)) * DIM + hh * HD;
    const __nv_bfloat16* Kgl = g_kl + ((size_t)(bb * SEQ)) * DIM + hh * HD;

    // ---- Q A-fragments (hi/lo bf16, pure loads, K padded to 80) ----
    uint32_t Qh[5][4], Ql[5][4];
    {
        const int r  = lane >> 2;
        const int c0 = (lane & 3) * 2;
#pragma unroll
        for (int ks = 0; ks < 5; ks++)
#pragma unroll
            for (int j = 0; j < 4; j++) {
                const int rr = r + (j & 1) * 8;
                const int cc = ks * 16 + c0 + ((j >> 1) & 1) * 8;
                uint32_t h = 0, l = 0;
                if (cc < HD) {
                    h = *(const uint32_t*)(Qgh + (size_t)rr * DIM + cc);
                    l = *(const uint32_t*)(Qgl + (size_t)rr * DIM + cc);
                }
                Qh[ks][j] = h; Ql[ks][j] = l;
            }
    }

    // zero pad cols [72,80) of all 4 K arrays (never touched by cp.async)
    for (int i = tid; i < 4 * 128; i += 256) {
        __nv_bfloat16* p = ksm + (i >> 7) * FS_TILE + (i & 127) * FS_KSTR + 72;
        *(uint2*)p = make_uint2(0, 0);
        *(uint2*)(p + 4) = make_uint2(0, 0);
    }

    const uint32_t kbase = smem_u32(ksm);

    auto issue = [&](int kb, int s) {
        const uint32_t dh = kbase + (uint32_t)(2 * s) * (FS_TILE * 2);
        const uint32_t dl = dh + FS_TILE * 2;
        const size_t g0 = (size_t)(kb * 128) * DIM;
        for (int idx = tid; idx < 128 * 9; idx += 256) {
            const int row = idx / 9;
            const int c8  = (idx % 9) * 8;
            const size_t ga = g0 + (size_t)row * DIM + c8;
            const uint32_t so = (uint32_t)(row * FS_KSTR + c8) * 2;
            cp16(dh + so, Kgh + ga);
            cp16(dl + so, Kgl + ga);
        }
        cp_commit();
    };

    issue(0, 0);
    issue(1, 1);

    float acc[8][2][4];
#pragma unroll
    for (int kb = 0; kb < 8; kb++)
#pragma unroll
        for (int nf = 0; nf < 2; nf++)
#pragma unroll
            for (int q = 0; q < 4; q++) acc[kb][nf][q] = 0.f;

    const uint32_t b_row = w * 16 + (lane & 7);
    const uint32_t b_off = ((lane >> 3) & 1) * 16;

#pragma unroll
    for (int kb = 0; kb < 8; kb++) {
        const int s = kb & 1;
        if (kb < 7) cp_wait<1>(); else cp_wait<0>();
        __syncthreads();
        const uint32_t kh = kbase + (uint32_t)(2 * s) * (FS_TILE * 2);
        const uint32_t kl = kh + FS_TILE * 2;
#pragma unroll
        for (int ks = 0; ks < 5; ks++) {
            uint32_t Bh[2][2], Bl[2][2];
#pragma unroll
            for (int nf = 0; nf < 2; nf++) {
                const uint32_t addr = (b_row + nf * 8) * (FS_KSTR * 2) + ks * 32 + b_off;
                ldsm_x2(Bh[nf][0], Bh[nf][1], kh + addr);
                ldsm_x2(Bl[nf][0], Bl[nf][1], kl + addr);
            }
#pragma unroll
            for (int nf = 0; nf < 2; nf++) {
                mma16816(acc[kb][nf], Qh[ks][0], Qh[ks][1], Qh[ks][2], Qh[ks][3],
                         Bh[nf][0], Bh[nf][1]);
                mma16816(acc[kb][nf], Ql[ks][0], Ql[ks][1], Ql[ks][2], Ql[ks][3],
                         Bh[nf][0], Bh[nf][1]);
                mma16816(acc[kb][nf], Qh[ks][0], Qh[ks][1], Qh[ks][2], Qh[ks][3],
                         Bl[nf][0], Bl[nf][1]);
            }
        }
        __syncthreads();
        if (kb + 2 < 8) issue(kb + 2, s);
    }

    // ---- softmax: exp, quad partial sums, cross-warp reduction ----
    float rs0 = 0.f, rs1 = 0.f;
#pragma unroll
    for (int kb = 0; kb < 8; kb++)
#pragma unroll
        for (int nf = 0; nf < 2; nf++) {
            acc[kb][nf][0] = __expf(acc[kb][nf][0] * SCALE_F);
            acc[kb][nf][1] = __expf(acc[kb][nf][1] * SCALE_F);
            acc[kb][nf][2] = __expf(acc[kb][nf][2] * SCALE_F);
            acc[kb][nf][3] = __expf(acc[kb][nf][3] * SCALE_F);
            rs0 += acc[kb][nf][0] + acc[kb][nf][1];
            rs1 += acc[kb][nf][2] + acc[kb][nf][3];
        }
    rs0 += __shfl_xor_sync(~0u, rs0, 1);
    rs0 += __shfl_xor_sync(~0u, rs0, 2);
    rs1 += __shfl_xor_sync(~0u, rs1, 1);
    rs1 += __shfl_xor_sync(~0u, rs1, 2);

    const int r = lane >> 2;
    if ((lane & 3) == 0) {
        srow[w][r]     = rs0;     // this warp's 128-column partial of row r
        srow[w][r + 8] = rs1;     // ... and row r+8
    }
    __syncthreads();
    float t0 = 0.f, t1 = 0.f;
#pragma unroll
    for (int ww = 0; ww < 8; ww++) {
        t0 += srow[ww][r];
        t1 += srow[ww][r + 8];
    }
    const float inv0 = 1.f / t0;
    const float inv1 = 1.f / t1;

    const int row0 = q0 + r;
    float* p0 = probs + ((size_t)bhx * SEQ + row0) * SEQ;
    float* p1 = p0 + 8 * SEQ;
#pragma unroll
    for (int kb = 0; kb < 8; kb++)
#pragma unroll
        for (int nf = 0; nf < 2; nf++) {
            const int col = kb * 128 + w * 16 + nf * 8 + (lane & 3) * 2;
            float2 v0, v1;
            v0.x = acc[kb][nf][0] * inv0; v0.y = acc[kb][nf][1] * inv0;
            v1.x = acc[kb][nf][2] * inv1; v1.y = acc[kb][nf][3] * inv1;
            *(float2*)(p0 + col) = v0;
            *(float2*)(p1 + col) = v1;
        }
}

// ===========================================================================
// Kernel 4: PV GEMM.  ctx = P @ V -> pre-split bf16 [B,N,D].
// ===========================================================================
#define PV_TS 72
#define PV_P_TILE (128 * PV_TS)
#define PV_V_TILE (96 * PV_TS)
#define PV_SMEM_BYTES ((2 * PV_P_TILE + 2 * PV_V_TILE) * 2)   // 64512

__global__ __launch_bounds__(256) void pv_tc_kernel(const float* __restrict__ probs)
{
    extern __shared__ __nv_bfloat16 pv_sm[];
    __nv_bfloat16* sPh = pv_sm;
    __nv_bfloat16* sPl = pv_sm + PV_P_TILE;
    __nv_bfloat16* sVh = pv_sm + 2 * PV_P_TILE;
    __nv_bfloat16* sVl = pv_sm + 2 * PV_P_TILE + PV_V_TILE;

    const int tid  = threadIdx.x;
    const int lane = tid & 31;
    const int wid  = tid >> 5;
    const int wm   = (wid >> 2) * 64;
    const int wn   = (wid & 3) * 24;
    const int m0 = blockIdx.x * 128;
    const int bhx = blockIdx.y;
    const int bb = bhx >> 4, hh = bhx & 15;

    const float* Pg = probs + (size_t)bhx * SEQ * SEQ;
    const __nv_bfloat16* Vgh = g_vh + (size_t)bb * SEQ * DIM + hh * HD;
    const __nv_bfloat16* Vgl = g_vl + (size_t)bb * SEQ * DIM + hh * HD;

    for (int i = tid; i < 24 * 18; i += 256) {
        const int r = 72 + i / 18;
        const int c = (i % 18) * 4;
        *(uint2*)(sVh + r * PV_TS + c) = make_uint2(0, 0);
        *(uint2*)(sVl + r * PV_TS + c) = make_uint2(0, 0);
    }

    const uint32_t ah = smem_u32(sPh), al = smem_u32(sPl);
    const uint32_t bh = smem_u32(sVh), bl = smem_u32(sVl);

    float acc[4][3][4];
#pragma unroll
    for (int i = 0; i < 4; i++)
#pragma unroll
        for (int j = 0; j < 3; j++)
#pragma unroll
            for (int q = 0; q < 4; q++) acc[i][j][q] = 0.f;

    const uint32_t a_off = (wm + (lane & 15)) * (PV_TS * 2) + (lane >> 4) * 16;
    const uint32_t b_row_base = wn + (lane & 7);
    const uint32_t b_off = ((lane >> 3) & 1) * 16;

    for (int k0 = 0; k0 < SEQ; k0 += 64) {
        __syncthreads();
#pragma unroll
        for (int t = 0; t < 8; t++) {
            const int idx = tid + t * 256;
            const int row = idx >> 4;
            const int c4  = (idx & 15) << 2;
            float4 pvv = *(const float4*)(Pg + (size_t)(m0 + row) * SEQ + k0 + c4);
            uint2 h, l;
            split8(h, l, pvv);
            *(uint2*)(sPh + row * PV_TS + c4) = h;
            *(uint2*)(sPl + row * PV_TS + c4) = l;
        }
        for (int idx = tid; idx < 64 * 36; idx += 256) {
            const int srow_ = idx / 36;
            const int c2   = (idx % 36) * 2;
            const uint32_t h = *(const uint32_t*)(Vgh + (size_t)(k0 + srow_) * DIM + c2);
            const uint32_t l = *(const uint32_t*)(Vgl + (size_t)(k0 + srow_) * DIM + c2);
            sVh[(c2 + 0) * PV_TS + srow_] = ((const __nv_bfloat16*)&h)[0];
            sVh[(c2 + 1) * PV_TS + srow_] = ((const __nv_bfloat16*)&h)[1];
            sVl[(c2 + 0) * PV_TS + srow_] = ((const __nv_bfloat16*)&l)[0];
            sVl[(c2 + 1) * PV_TS + srow_] = ((const __nv_bfloat16*)&l)[1];
        }
        __syncthreads();

#pragma unroll
        for (int ks = 0; ks < 4; ks++) {
            uint32_t Ah[4][4], Al[4][4], Bh[3][2], Bl[3][2];
#pragma unroll
            for (int mf = 0; mf < 4; mf++) {
                const uint32_t addr = a_off + mf * 16 * (PV_TS * 2) + ks * 32;
                ldsm_x4(Ah[mf][0], Ah[mf][1], Ah[mf][2], Ah[mf][3], ah + addr);
                ldsm_x4(Al[mf][0], Al[mf][1], Al[mf][2], Al[mf][3], al + addr);
            }
#pragma unroll
            for (int nf = 0; nf < 3; nf++) {
                const uint32_t addr = (b_row_base + nf * 8) * (PV_TS * 2) + ks * 32 + b_off;
                ldsm_x2(Bh[nf][0], Bh[nf][1], bh + addr);
                ldsm_x2(Bl[nf][0], Bl[nf][1], bl + addr);
            }
#pragma unroll
            for (int mf = 0; mf < 4; mf++)
#pragma unroll
                for (int nf = 0; nf < 3; nf++) {
                    mma16816(acc[mf][nf], Ah[mf][0], Ah[mf][1], Ah[mf][2], Ah[mf][3],
                             Bh[nf][0], Bh[nf][1]);
                    mma16816(acc[mf][nf], Al[mf][0], Al[mf][1], Al[mf][2], Al[mf][3],
                             Bh[nf][0], Bh[nf][1]);
                    mma16816(acc[mf][nf], Ah[mf][0], Ah[mf][1], Ah[mf][2], Ah[mf][3],
                             Bl[nf][0], Bl[nf][1]);
                }
        }
    }

    const int r_base = m0 + wm + (lane >> 2);
    const int c_base = wn + (lane & 3) * 2;
#pragma unroll
    for (int mf = 0; mf < 4; mf++)
#pragma unroll
        for (int nf = 0; nf < 3; nf++) {
            const int col = c_base + nf * 8;
            if (col < HD) {
#pragma unroll
                for (int half = 0; half < 2; half++) {
                    const int row = r_base + mf * 16 + half * 8;
                    const size_t ga = ((size_t)bb * SEQ + row) * DIM + hh * HD + col;
                    uint32_t hi, lo;
                    split2(hi, lo, acc[mf][nf][half * 2 + 0],
                           acc[mf][nf][half * 2 + 1]);
                    *(uint32_t*)(g_ch + ga) = hi;
                    *(uint32_t*)(g_cl + ga) = lo;
                }
            }
        }
}

// ---------------------------------------------------------------------------
extern "C" void kernel_launch(void* const* d_in, const int* in_sizes, int n_in,
                              void* d_out, int out_size)
{
    const float* x  = (const float*)d_in[0];
    const float* qw = (const float*)d_in[1];
    const float* qb = (const float*)d_in[2];
    const float* kw = (const float*)d_in[3];
    const float* kb = (const float*)d_in[4];
    const float* vw = (const float*)d_in[5];
    const float* vb = (const float*)d_in[6];
    const float* ow = (const float*)d_in[7];
    const float* ob = (const float*)d_in[8];

    float* out   = (float*)d_out;            // [B,N,D]
    float* probs = out + OUT_ELEMS;          // [B,H,N,N]

    cudaFuncSetAttribute(qkv_tc_kernel,
                         cudaFuncAttributeMaxDynamicSharedMemorySize, GT_SMEM_BYTES);
    cudaFuncSetAttribute(oproj_tc_kernel,
                         cudaFuncAttributeMaxDynamicSharedMemorySize, GT_SMEM_BYTES);
    cudaFuncSetAttribute(fused_scores_softmax_kernel,
                         cudaFuncAttributeMaxDynamicSharedMemorySize, FS_SMEM);
    cudaFuncSetAttribute(pv_tc_kernel,
                         cudaFuncAttributeMaxDynamicSharedMemorySize, PV_SMEM_BYTES);

    prep_kernel<<<(PREP_TOTAL + 255) / 256, 256>>>(x, qw, kw, vw, ow);

    dim3 gq(DIM / 128, MTOT / 128, 3);       // (9, 64, 3)
    qkv_tc_kernel<<<gq, 256, GT_SMEM_BYTES>>>(qb, kb, vb);

    dim3 gs(SEQ / 16, BD * NH);              // (64, 128)
    fused_scores_softmax_kernel<<<gs, 256, FS_SMEM>>>(probs);

    dim3 gp(SEQ / 128, BD * NH);             // (8, 128)
    pv_tc_kernel<<<gp, 256, PV_SMEM_BYTES>>>(probs);

    dim3 go(DIM / 128, MTOT / 128);          // (9, 64)
    oproj_tc_kernel<<<go, 256, GT_SMEM_BYTES>>>(ob, out);
}

// round 13
// speedup vs baseline: 1.3422x; 1.3422x over previous
#include <cuda_runtime.h>
#include <cuda_bf16.h>
#include <cstdint>
#include <math.h>

// ---------------------------------------------------------------------------
// SiglipAttention: B=8, N=1024, D=1152, H=16, Hd=72
// Outputs (concatenated in d_out): out [B,N,D] fp32, attn_probs [B,H,N,N] fp32
// ---------------------------------------------------------------------------

#define BD   8
#define SEQ  1024
#define DIM  1152
#define NH   16
#define HD   72
#define MTOT (BD * SEQ)                 // 8192
#define QKV_ELEMS (BD * NH * SEQ * HD)  // 9437184
#define OUT_ELEMS (BD * SEQ * DIM)      // 9437184
#define WELEMS (DIM * DIM)              // 1327104
#define PROB_ELEMS ((size_t)BD * NH * SEQ * SEQ)  // 134217728
#define SCALE_F 0.117851130197757931f   // 72^-0.5

// Scratch (allocation-free rule: __device__ globals).  All MMA operands are
// PRE-SPLIT hi/lo bf16.  Q/K/V in [B,H,N,Hd] (head-contiguous — dense rows);
// ctx in [B,N,D] so oproj's A side is a plain [M,DIM] matrix.
__device__ __nv_bfloat16 g_xh[OUT_ELEMS],  g_xl[OUT_ELEMS];    // x
__device__ __nv_bfloat16 g_wh[4][WELEMS],  g_wl[4][WELEMS];    // q,k,v,o weights
__device__ __nv_bfloat16 g_qh[QKV_ELEMS],  g_ql[QKV_ELEMS];    // Q
__device__ __nv_bfloat16 g_kh[QKV_ELEMS],  g_kl[QKV_ELEMS];    // K
__device__ __nv_bfloat16 g_vh[QKV_ELEMS],  g_vl[QKV_ELEMS];    // V
__device__ __nv_bfloat16 g_ch[OUT_ELEMS],  g_cl[OUT_ELEMS];    // ctx
__device__ __nv_bfloat16 g_ph[PROB_ELEMS], g_pl[PROB_ELEMS];   // probs pre-split

// ===========================================================================
// HMMA + cp.async helpers (sm_80+ paths; tcgen05 unavailable on sm_103 base)
// ===========================================================================
__device__ __forceinline__ uint32_t smem_u32(const void* p) {
    uint32_t a;
    asm("{ .reg .u64 t; cvta.to.shared.u64 t, %1; cvt.u32.u64 %0, t; }"
        : "=r"(a) : "l"(p));
    return a;
}
__device__ __forceinline__ void ldsm_x4(uint32_t& r0, uint32_t& r1,
                                        uint32_t& r2, uint32_t& r3, uint32_t a) {
    asm volatile("ldmatrix.sync.aligned.m8n8.x4.shared.b16 {%0,%1,%2,%3}, [%4];"
                 : "=r"(r0), "=r"(r1), "=r"(r2), "=r"(r3) : "r"(a));
}
__device__ __forceinline__ void ldsm_x2(uint32_t& r0, uint32_t& r1, uint32_t a) {
    asm volatile("ldmatrix.sync.aligned.m8n8.x2.shared.b16 {%0,%1}, [%2];"
                 : "=r"(r0), "=r"(r1) : "r"(a));
}
__device__ __forceinline__ void ldsm_x2_trans(uint32_t& r0, uint32_t& r1, uint32_t a) {
    asm volatile("ldmatrix.sync.aligned.m8n8.x2.trans.shared.b16 {%0,%1}, [%2];"
                 : "=r"(r0), "=r"(r1) : "r"(a));
}
__device__ __forceinline__ void mma16816(float* c,
                                         uint32_t a0, uint32_t a1, uint32_t a2, uint32_t a3,
                                         uint32_t b0, uint32_t b1) {
    asm volatile(
        "mma.sync.aligned.m16n8k16.row.col.f32.bf16.bf16.f32 "
        "{%0,%1,%2,%3}, {%4,%5,%6,%7}, {%8,%9}, {%0,%1,%2,%3};"
        : "+f"(c[0]), "+f"(c[1]), "+f"(c[2]), "+f"(c[3])
        : "r"(a0), "r"(a1), "r"(a2), "r"(a3), "r"(b0), "r"(b1));
}
__device__ __forceinline__ void cp16(uint32_t s, const void* g) {
    asm volatile("cp.async.ca.shared.global [%0], [%1], 16;"
                 :: "r"(s), "l"(__cvta_generic_to_global(g)));
}
__device__ __forceinline__ void cp_commit() {
    asm volatile("cp.async.commit_group;");
}
template <int N>
__device__ __forceinline__ void cp_wait() {
    asm volatile("cp.async.wait_group %0;" :: "n"(N));
}

// split fp32x4 -> hi bf16x4 + lo bf16x4 (packed as uint2 each)
__device__ __forceinline__ void split8(uint2& hi, uint2& lo, float4 v) {
    __nv_bfloat162 h01 = __floats2bfloat162_rn(v.x, v.y);
    __nv_bfloat162 h23 = __floats2bfloat162_rn(v.z, v.w);
    float rx = v.x - __bfloat162float(h01.x);
    float ry = v.y - __bfloat162float(h01.y);
    float rz = v.z - __bfloat162float(h23.x);
    float rw = v.w - __bfloat162float(h23.y);
    hi = make_uint2(*(uint32_t*)&h01, *(uint32_t*)&h23);
    __nv_bfloat162 l01 = __floats2bfloat162_rn(rx, ry);
    __nv_bfloat162 l23 = __floats2bfloat162_rn(rz, rw);
    lo = make_uint2(*(uint32_t*)&l01, *(uint32_t*)&l23);
}
__device__ __forceinline__ void split2(uint32_t& hi, uint32_t& lo, float x, float y) {
    __nv_bfloat162 h = __floats2bfloat162_rn(x, y);
    float rx = x - __bfloat162float(h.x);
    float ry = y - __bfloat162float(h.y);
    hi = *(uint32_t*)&h;
    __nv_bfloat162 l = __floats2bfloat162_rn(rx, ry);
    lo = *(uint32_t*)&l;
}

// ===========================================================================
// Kernel 0: pre-split x and the 4 weight matrices (once).
// ===========================================================================
#define X_F4   (OUT_ELEMS / 4)
#define W_F4   (WELEMS / 4)
#define PREP_TOTAL (X_F4 + 4 * W_F4)

__global__ __launch_bounds__(256) void prep_kernel(
    const float* __restrict__ x,
    const float* __restrict__ qw, const float* __restrict__ kw,
    const float* __restrict__ vw, const float* __restrict__ ow)
{
    const size_t i = (size_t)blockIdx.x * 256 + threadIdx.x;
    if (i >= PREP_TOTAL) return;
    const float* src;
    __nv_bfloat16 *dh, *dl;
    size_t e;
    if (i < X_F4) {
        src = x; dh = g_xh; dl = g_xl; e = i;
    } else {
        const size_t wi = i - X_F4;
        const int wsel = (int)(wi / W_F4);
        e = wi % W_F4;
        src = (wsel == 0) ? qw : (wsel == 1) ? kw : (wsel == 2) ? vw : ow;
        dh = g_wh[wsel]; dl = g_wl[wsel];
    }
    float4 v = *(const float4*)(src + e * 4);
    uint2 h, l;
    split8(h, l, v);
    *(uint2*)(dh + e * 4) = h;
    *(uint2*)(dl + e * 4) = l;
}

// ===========================================================================
// Common bf16x3 HMMA GEMM core (R8-proven, non-pipelined, static smem):
//   y[128,128]tile = A[M,K] @ W[N,K]^T ; staging is pure uint4 copies.
// MODE 0: head-scatter epilogue -> hi/lo bf16 [B,H,N,Hd] (qkv)
// MODE 1: plain fp32 [M,DIM] epilogue (o-proj)
// ===========================================================================
#define TSTR 40   // bf16 elements per smem row (80 bytes, conflict-free)

template <int MODE>
__device__ __forceinline__ void tc_gemm_tile(
    const __nv_bfloat16* __restrict__ Agh, const __nv_bfloat16* __restrict__ Agl,
    const __nv_bfloat16* __restrict__ Wgh, const __nv_bfloat16* __restrict__ Wgl,
    const float* __restrict__ bias,
    float* __restrict__ dst, __nv_bfloat16* __restrict__ dsth,
    __nv_bfloat16* __restrict__ dstl,
    int m0, int n0)
{
    __shared__ __nv_bfloat16 sAh[128 * TSTR], sAl[128 * TSTR];
    __shared__ __nv_bfloat16 sBh[128 * TSTR], sBl[128 * TSTR];

    const int tid  = threadIdx.x;
    const int lane = tid & 31;
    const int wid  = tid >> 5;
    const int wm   = (wid >> 2) * 64;
    const int wn   = (wid & 3) * 32;

    const uint32_t ah = smem_u32(sAh), al = smem_u32(sAl);
    const uint32_t bh = smem_u32(sBh), bl = smem_u32(sBl);

    float acc[4][4][4];
#pragma unroll
    for (int i = 0; i < 4; i++)
#pragma unroll
        for (int j = 0; j < 4; j++)
#pragma unroll
            for (int q = 0; q < 4; q++) acc[i][j][q] = 0.f;

    const uint32_t a_off = (wm + (lane & 15)) * (TSTR * 2) + (lane >> 4) * 16;
    const uint32_t b_row_base = wn + (lane & 7);
    const uint32_t b_off = ((lane >> 3) & 1) * 16;

    for (int k0 = 0; k0 < DIM; k0 += 32) {
        __syncthreads();
#pragma unroll
        for (int t = 0; t < 2; t++) {
            const int idx = tid + t * 256;        // 0..511
            const int row = idx >> 2;
            const int c8  = (idx & 3) * 8;
            const size_t ga = (size_t)(m0 + row) * DIM + k0 + c8;
            const size_t gb = (size_t)(n0 + row) * DIM + k0 + c8;
            *(uint4*)(sAh + row * TSTR + c8) = *(const uint4*)(Agh + ga);
            *(uint4*)(sAl + row * TSTR + c8) = *(const uint4*)(Agl + ga);
            *(uint4*)(sBh + row * TSTR + c8) = *(const uint4*)(Wgh + gb);
            *(uint4*)(sBl + row * TSTR + c8) = *(const uint4*)(Wgl + gb);
        }
        __syncthreads();

#pragma unroll
        for (int ks = 0; ks < 2; ks++) {
            uint32_t Ah[4][4], Al[4][4], Bh[4][2], Bl[4][2];
#pragma unroll
            for (int mf = 0; mf < 4; mf++) {
                const uint32_t addr = a_off + mf * 16 * (TSTR * 2) + ks * 32;
                ldsm_x4(Ah[mf][0], Ah[mf][1], Ah[mf][2], Ah[mf][3], ah + addr);
                ldsm_x4(Al[mf][0], Al[mf][1], Al[mf][2], Al[mf][3], al + addr);
            }
#pragma unroll
            for (int nf = 0; nf < 4; nf++) {
                const uint32_t addr = (b_row_base + nf * 8) * (TSTR * 2) + ks * 32 + b_off;
                ldsm_x2(Bh[nf][0], Bh[nf][1], bh + addr);
                ldsm_x2(Bl[nf][0], Bl[nf][1], bl + addr);
            }
#pragma unroll
            for (int mf = 0; mf < 4; mf++)
#pragma unroll
                for (int nf = 0; nf < 4; nf++) {
                    mma16816(acc[mf][nf], Ah[mf][0], Ah[mf][1], Ah[mf][2], Ah[mf][3],
                             Bh[nf][0], Bh[nf][1]);
                    mma16816(acc[mf][nf], Al[mf][0], Al[mf][1], Al[mf][2], Al[mf][3],
                             Bh[nf][0], Bh[nf][1]);
                    mma16816(acc[mf][nf], Ah[mf][0], Ah[mf][1], Ah[mf][2], Ah[mf][3],
                             Bl[nf][0], Bl[nf][1]);
                }
        }
    }

    const int r_base = m0 + wm + (lane >> 2);
    const int c_base = n0 + wn + (lane & 3) * 2;
#pragma unroll
    for (int mf = 0; mf < 4; mf++) {
#pragma unroll
        for (int nf = 0; nf < 4; nf++) {
            const int col = c_base + nf * 8;
            const float bx = bias[col], by = bias[col + 1];
#pragma unroll
            for (int half = 0; half < 2; half++) {
                const int row = r_base + mf * 16 + half * 8;
                const float vx = acc[mf][nf][half * 2 + 0] + bx;
                const float vy = acc[mf][nf][half * 2 + 1] + by;
                if (MODE == 0) {
                    const int bb = row >> 10, n = row & 1023;
                    const int hdh = col / HD, hd = col % HD;
                    const size_t ga = ((size_t)(bb * NH + hdh) * SEQ + n) * HD + hd;
                    uint32_t hi, lo;
                    split2(hi, lo, vx, vy);
                    *(uint32_t*)(dsth + ga) = hi;
                    *(uint32_t*)(dstl + ga) = lo;
                } else {
                    float2 v; v.x = vx; v.y = vy;
                    *(float2*)(dst + (size_t)row * DIM + col) = v;
                }
            }
        }
    }
}

// Kernel 1: QKV projection -> pre-split bf16 head layout [B,H,N,Hd]
__global__ __launch_bounds__(256) void qkv_tc_kernel(
    const float* __restrict__ qb, const float* __restrict__ kb,
    const float* __restrict__ vb)
{
    const int proj = blockIdx.z;
    const float* bias = (proj == 0) ? qb : (proj == 1) ? kb : vb;
    __nv_bfloat16* dh = (proj == 0) ? g_qh : (proj == 1) ? g_kh : g_vh;
    __nv_bfloat16* dl = (proj == 0) ? g_ql : (proj == 1) ? g_kl : g_vl;
    tc_gemm_tile<0>(g_xh, g_xl, g_wh[proj], g_wl[proj], bias,
                    nullptr, dh, dl, blockIdx.y * 128, blockIdx.x * 128);
}

// Kernel 5: O projection (ctx pre-split by pv) -> fp32 out
__global__ __launch_bounds__(256) void oproj_tc_kernel(
    const float* __restrict__ ob, float* __restrict__ out)
{
    tc_gemm_tile<1>(g_ch, g_cl, g_wh[3], g_wl[3], ob,
                    out, nullptr, nullptr, blockIdx.y * 128, blockIdx.x * 128);
}

// ===========================================================================
// Kernel 2: FUSED scores + softmax, register-resident S, Q in SMEM.
//   16 q-rows x 1024 keys per CTA.  Q staged once to smem (re-ldsm'd per
//   k-tile; volatile asm prevents hoisting -> no 40-reg Q footprint, no
//   spills under launch_bounds(256,2)).  K double-buffered via cp.async.
//   Row sums: quad-reduce + cross-warp smem reduce.  No max pass (exact).
//   ALSO writes pre-split P (hi/lo bf16) for the pv kernel.
// ===========================================================================
#define FS_KSTR 88
#define FS_TILE (128 * FS_KSTR)                  // per K array
#define FS_QOFF (4 * FS_TILE)                    // Q tiles after K stages
#define FS_SMEM ((4 * FS_TILE + 2 * 16 * FS_KSTR) * 2)   // 95744 bytes

__global__ __launch_bounds__(256, 2) void fused_scores_softmax_kernel(
    float* __restrict__ probs)
{
    extern __shared__ __nv_bfloat16 ksm[];
    __shared__ float srow[8][16];
    const int tid  = threadIdx.x;
    const int lane = tid & 31;
    const int w    = tid >> 5;
    const int q0   = blockIdx.x * 16;
    const int bhx  = blockIdx.y;

    const __nv_bfloat16* Qgh = g_qh + ((size_t)bhx * SEQ + q0) * HD;
    const __nv_bfloat16* Qgl = g_ql + ((size_t)bhx * SEQ + q0) * HD;
    const __nv_bfloat16* Kgh = g_kh + (size_t)bhx * SEQ * HD;
    const __nv_bfloat16* Kgl = g_kl + (size_t)bhx * SEQ * HD;

    __nv_bfloat16* Qsh = ksm + FS_QOFF;
    __nv_bfloat16* Qsl = Qsh + 16 * FS_KSTR;

    // stage Q (pure copies) + zero Q pads [72,80)
    for (int idx = tid; idx < 16 * 9; idx += 256) {
        const int row = idx / 9;
        const int c8  = (idx % 9) * 8;
        *(uint4*)(Qsh + row * FS_KSTR + c8) =
            *(const uint4*)(Qgh + (size_t)row * HD + c8);
        *(uint4*)(Qsl + row * FS_KSTR + c8) =
            *(const uint4*)(Qgl + (size_t)row * HD + c8);
    }
    for (int i = tid; i < 2 * 16; i += 256) {
        __nv_bfloat16* p = ((i & 1) ? Qsl : Qsh) + (i >> 1) * FS_KSTR + 72;
        *(uint2*)p = make_uint2(0, 0);
        *(uint2*)(p + 4) = make_uint2(0, 0);
    }
    // zero K pads [72,80) of all 4 K arrays
    for (int i = tid; i < 4 * 128; i += 256) {
        __nv_bfloat16* p = ksm + (i >> 7) * FS_TILE + (i & 127) * FS_KSTR + 72;
        *(uint2*)p = make_uint2(0, 0);
        *(uint2*)(p + 4) = make_uint2(0, 0);
    }

    const uint32_t kbase = smem_u32(ksm);
    const uint32_t qh_base = smem_u32(Qsh);
    const uint32_t ql_base = smem_u32(Qsl);

    auto issue = [&](int kb, int s) {
        const uint32_t dh = kbase + (uint32_t)(2 * s) * (FS_TILE * 2);
        const uint32_t dl = dh + FS_TILE * 2;
        for (int idx = tid; idx < 128 * 9; idx += 256) {
            const int row = idx / 9;
            const int c8  = (idx % 9) * 8;
            const size_t ga = (size_t)(kb * 128 + row) * HD + c8;
            const uint32_t so = (uint32_t)(row * FS_KSTR + c8) * 2;
            cp16(dh + so, Kgh + ga);
            cp16(dl + so, Kgl + ga);
        }
        cp_commit();
    };

    issue(0, 0);
    issue(1, 1);

    float acc[8][2][4];
#pragma unroll
    for (int kb = 0; kb < 8; kb++)
#pragma unroll
        for (int nf = 0; nf < 2; nf++)
#pragma unroll
            for (int q = 0; q < 4; q++) acc[kb][nf][q] = 0.f;

    const uint32_t q_off = (lane & 15) * (FS_KSTR * 2) + (lane >> 4) * 16;
    const uint32_t b_row = w * 16 + (lane & 7);
    const uint32_t b_off = ((lane >> 3) & 1) * 16;

#pragma unroll
    for (int kb = 0; kb < 8; kb++) {
        const int s = kb & 1;
        if (kb < 7) cp_wait<1>(); else cp_wait<0>();
        __syncthreads();
        const uint32_t kh = kbase + (uint32_t)(2 * s) * (FS_TILE * 2);
        const uint32_t kl = kh + FS_TILE * 2;
#pragma unroll
        for (int ks = 0; ks < 5; ks++) {
            uint32_t QA[4], QB[4], Bh[2][2], Bl[2][2];
            ldsm_x4(QA[0], QA[1], QA[2], QA[3], qh_base + q_off + ks * 32);
            ldsm_x4(QB[0], QB[1], QB[2], QB[3], ql_base + q_off + ks * 32);
#pragma unroll
            for (int nf = 0; nf < 2; nf++) {
                const uint32_t addr = (b_row + nf * 8) * (FS_KSTR * 2) + ks * 32 + b_off;
                ldsm_x2(Bh[nf][0], Bh[nf][1], kh + addr);
                ldsm_x2(Bl[nf][0], Bl[nf][1], kl + addr);
            }
#pragma unroll
            for (int nf = 0; nf < 2; nf++) {
                mma16816(acc[kb][nf], QA[0], QA[1], QA[2], QA[3], Bh[nf][0], Bh[nf][1]);
                mma16816(acc[kb][nf], QB[0], QB[1], QB[2], QB[3], Bh[nf][0], Bh[nf][1]);
                mma16816(acc[kb][nf], QA[0], QA[1], QA[2], QA[3], Bl[nf][0], Bl[nf][1]);
            }
        }
        __syncthreads();
        if (kb + 2 < 8) issue(kb + 2, s);
    }

    // ---- softmax: exp, quad partial sums, cross-warp reduction ----
    float rs0 = 0.f, rs1 = 0.f;
#pragma unroll
    for (int kb = 0; kb < 8; kb++)
#pragma unroll
        for (int nf = 0; nf < 2; nf++) {
            acc[kb][nf][0] = __expf(acc[kb][nf][0] * SCALE_F);
            acc[kb][nf][1] = __expf(acc[kb][nf][1] * SCALE_F);
            acc[kb][nf][2] = __expf(acc[kb][nf][2] * SCALE_F);
            acc[kb][nf][3] = __expf(acc[kb][nf][3] * SCALE_F);
            rs0 += acc[kb][nf][0] + acc[kb][nf][1];
            rs1 += acc[kb][nf][2] + acc[kb][nf][3];
        }
    rs0 += __shfl_xor_sync(~0u, rs0, 1);
    rs0 += __shfl_xor_sync(~0u, rs0, 2);
    rs1 += __shfl_xor_sync(~0u, rs1, 1);
    rs1 += __shfl_xor_sync(~0u, rs1, 2);

    const int r = lane >> 2;
    if ((lane & 3) == 0) {
        srow[w][r]     = rs0;
        srow[w][r + 8] = rs1;
    }
    __syncthreads();
    float t0 = 0.f, t1 = 0.f;
#pragma unroll
    for (int ww = 0; ww < 8; ww++) {
        t0 += srow[ww][r];
        t1 += srow[ww][r + 8];
    }
    const float inv0 = 1.f / t0;
    const float inv1 = 1.f / t1;

    const size_t rbase0 = (size_t)bhx * SEQ + q0 + r;
    float* p0 = probs + rbase0 * SEQ;
    float* p1 = p0 + 8 * SEQ;
    __nv_bfloat16* ph0 = g_ph + rbase0 * SEQ;
    __nv_bfloat16* ph1 = ph0 + 8 * SEQ;
    __nv_bfloat16* pl0 = g_pl + rbase0 * SEQ;
    __nv_bfloat16* pl1 = pl0 + 8 * SEQ;
#pragma unroll
    for (int kb = 0; kb < 8; kb++)
#pragma unroll
        for (int nf = 0; nf < 2; nf++) {
            const int col = kb * 128 + w * 16 + nf * 8 + (lane & 3) * 2;
            float2 v0, v1;
            v0.x = acc[kb][nf][0] * inv0; v0.y = acc[kb][nf][1] * inv0;
            v1.x = acc[kb][nf][2] * inv1; v1.y = acc[kb][nf][3] * inv1;
            *(float2*)(p0 + col) = v0;
            *(float2*)(p1 + col) = v1;
            uint32_t hi, lo;
            split2(hi, lo, v0.x, v0.y);
            *(uint32_t*)(ph0 + col) = hi;
            *(uint32_t*)(pl0 + col) = lo;
            split2(hi, lo, v1.x, v1.y);
            *(uint32_t*)(ph1 + col) = hi;
            *(uint32_t*)(pl1 + col) = lo;
        }
}

// ===========================================================================
// Kernel 4: PV GEMM, fully cp.async double-buffered (P pre-split by fused).
//   ctx = P[1024,1024] @ V[1024,72] -> pre-split bf16 [B,N,D].
//   P as A [m][k] (stride 72); V k-major [k][hd] (stride 72) fed to the B
//   side via ldmatrix.trans.  Warps: 2m x 4n(24); n>=72 warps idle on MMA.
// ===========================================================================
#define PV_STR 72
#define PV_P_ARR (128 * PV_STR)                  // 9216 el
#define PV_V_ARR (64 * PV_STR)                   // 4608 el
#define PV_STAGE (2 * PV_P_ARR + 2 * PV_V_ARR)   // 27648 el
#define PV_SMEM (2 * PV_STAGE * 2)               // 110592 bytes

__global__ __launch_bounds__(256, 2) void pv_tc_kernel()
{
    extern __shared__ __nv_bfloat16 psm[];
    const int tid  = threadIdx.x;
    const int lane = tid & 31;
    const int wid  = tid >> 5;
    const int wm   = (wid >> 2) * 64;
    const int wn   = (wid & 3) * 24;
    const int m0 = blockIdx.x * 128;
    const int bhx = blockIdx.y;
    const int bb = bhx >> 4, hh = bhx & 15;

    const __nv_bfloat16* Pgh = g_ph + (size_t)bhx * SEQ * SEQ;
    const __nv_bfloat16* Pgl = g_pl + (size_t)bhx * SEQ * SEQ;
    const __nv_bfloat16* Vgh = g_vh + (size_t)bhx * SEQ * HD;
    const __nv_bfloat16* Vgl = g_vl + (size_t)bhx * SEQ * HD;

    const uint32_t sbase = smem_u32(psm);

    auto issue = [&](int c, int s) {
        const uint32_t st = sbase + (uint32_t)s * (PV_STAGE * 2);
        const uint32_t ph = st;
        const uint32_t pl = st + PV_P_ARR * 2;
        const uint32_t vh = st + 2 * PV_P_ARR * 2;
        const uint32_t vl = vh + PV_V_ARR * 2;
        // P tile 128 x 64 (dense 128B rows)
#pragma unroll
        for (int t = 0; t < 4; t++) {
            const int idx = tid + t * 256;       // 0..1023
            const int row = idx >> 3;
            const int c8  = (idx & 7) * 8;
            const size_t ga = (size_t)(m0 + row) * SEQ + c * 64 + c8;
            const uint32_t so = (uint32_t)(row * PV_STR + c8) * 2;
            cp16(ph + so, Pgh + ga);
            cp16(pl + so, Pgl + ga);
        }
        // V tile 64 x 72, k-major (dense 144B rows)
        for (int idx = tid; idx < 64 * 9; idx += 256) {
            const int row = idx / 9;
            const int c8  = (idx % 9) * 8;
            const size_t ga = (size_t)(c * 64 + row) * HD + c8;
            const uint32_t so = (uint32_t)(row * PV_STR + c8) * 2;
            cp16(vh + so, Vgh + ga);
            cp16(vl + so, Vgl + ga);
        }
        cp_commit();
    };

    issue(0, 0);
    issue(1, 1);

    float acc[4][3][4];
#pragma unroll
    for (int i = 0; i < 4; i++)
#pragma unroll
        for (int j = 0; j < 3; j++)
#pragma unroll
            for (int q = 0; q < 4; q++) acc[i][j][q] = 0.f;

    const uint32_t a_off = (wm + (lane & 15)) * (PV_STR * 2) + (lane >> 4) * 16;

    for (int c = 0; c < 16; c++) {
        const int s = c & 1;
        if (c + 1 < 16) cp_wait<1>(); else cp_wait<0>();
        __syncthreads();
        const uint32_t st = sbase + (uint32_t)s * (PV_STAGE * 2);
        const uint32_t ph = st;
        const uint32_t pl = st + PV_P_ARR * 2;
        const uint32_t vh = st + 2 * PV_P_ARR * 2;
        const uint32_t vl = vh + PV_V_ARR * 2;

#pragma unroll
        for (int ks = 0; ks < 4; ks++) {
            uint32_t Ah[4][4], Al[4][4], Bh[3][2], Bl[3][2];
#pragma unroll
            for (int mf = 0; mf < 4; mf++) {
                const uint32_t addr = a_off + mf * 16 * (PV_STR * 2) + ks * 32;
                ldsm_x4(Ah[mf][0], Ah[mf][1], Ah[mf][2], Ah[mf][3], ph + addr);
                ldsm_x4(Al[mf][0], Al[mf][1], Al[mf][2], Al[mf][3], pl + addr);
            }
#pragma unroll
            for (int nf = 0; nf < 3; nf++) {
                if (wn + nf * 8 < HD) {
                    const uint32_t addr = (ks * 16 + (lane & 15)) * (PV_STR * 2)
                                        + (wn + nf * 8) * 2;
                    ldsm_x2_trans(Bh[nf][0], Bh[nf][1], vh + addr);
                    ldsm_x2_trans(Bl[nf][0], Bl[nf][1], vl + addr);
                }
            }
#pragma unroll
            for (int mf = 0; mf < 4; mf++)
#pragma unroll
                for (int nf = 0; nf < 3; nf++) {
                    if (wn + nf * 8 < HD) {
                        mma16816(acc[mf][nf], Ah[mf][0], Ah[mf][1], Ah[mf][2], Ah[mf][3],
                                 Bh[nf][0], Bh[nf][1]);
                        mma16816(acc[mf][nf], Al[mf][0], Al[mf][1], Al[mf][2], Al[mf][3],
                                 Bh[nf][0], Bh[nf][1]);
                        mma16816(acc[mf][nf], Ah[mf][0], Ah[mf][1], Ah[mf][2], Ah[mf][3],
                                 Bl[nf][0], Bl[nf][1]);
                    }
                }
        }
        __syncthreads();
        if (c + 2 < 16) issue(c + 2, s);
    }

    // epilogue: split ctx to hi/lo bf16 [B,N,D] (consumed by oproj)
    const int r_base = m0 + wm + (lane >> 2);
    const int c_base = wn + (lane & 3) * 2;
#pragma unroll
    for (int mf = 0; mf < 4; mf++)
#pragma unroll
        for (int nf = 0; nf < 3; nf++) {
            const int col = c_base + nf * 8;
            if (col < HD) {
#pragma unroll
                for (int half = 0; half < 2; half++) {
                    const int row = r_base + mf * 16 + half * 8;
                    const size_t ga = ((size_t)bb * SEQ + row) * DIM + hh * HD + col;
                    uint32_t hi, lo;
                    split2(hi, lo, acc[mf][nf][half * 2 + 0],
                           acc[mf][nf][half * 2 + 1]);
                    *(uint32_t*)(g_ch + ga) = hi;
                    *(uint32_t*)(g_cl + ga) = lo;
                }
            }
        }
}

// ---------------------------------------------------------------------------
extern "C" void kernel_launch(void* const* d_in, const int* in_sizes, int n_in,
                              void* d_out, int out_size)
{
    const float* x  = (const float*)d_in[0];
    const float* qw = (const float*)d_in[1];
    const float* qb = (const float*)d_in[2];
    const float* kw = (const float*)d_in[3];
    const float* kb = (const float*)d_in[4];
    const float* vw = (const float*)d_in[5];
    const float* vb = (const float*)d_in[6];
    const float* ow = (const float*)d_in[7];
    const float* ob = (const float*)d_in[8];

    float* out   = (float*)d_out;            // [B,N,D]
    float* probs = out + OUT_ELEMS;          // [B,H,N,N]

    cudaFuncSetAttribute(fused_scores_softmax_kernel,
                         cudaFuncAttributeMaxDynamicSharedMemorySize, FS_SMEM);
    cudaFuncSetAttribute(pv_tc_kernel,
                         cudaFuncAttributeMaxDynamicSharedMemorySize, PV_SMEM);

    prep_kernel<<<(PREP_TOTAL + 255) / 256, 256>>>(x, qw, kw, vw, ow);

    dim3 gq(DIM / 128, MTOT / 128, 3);       // (9, 64, 3)
    qkv_tc_kernel<<<gq, 256>>>(qb, kb, vb);

    dim3 gs(SEQ / 16, BD * NH);              // (64, 128)
    fused_scores_softmax_kernel<<<gs, 256, FS_SMEM>>>(probs);

    dim3 gp(SEQ / 128, BD * NH);             // (8, 128)
    pv_tc_kernel<<<gp, 256, PV_SMEM>>>();

    dim3 go(DIM / 128, MTOT / 128);          // (9, 64)
    oproj_tc_kernel<<<go, 256>>>(ob, out);
}

// round 14
// speedup vs baseline: 1.5317x; 1.1412x over previous
#include <cuda_runtime.h>
#include <cuda_bf16.h>
#include <cstdint>
#include <math.h>

// ---------------------------------------------------------------------------
// SiglipAttention: B=8, N=1024, D=1152, H=16, Hd=72
// Outputs (concatenated in d_out): out [B,N,D] fp32, attn_probs [B,H,N,N] fp32
// ---------------------------------------------------------------------------

#define BD   8
#define SEQ  1024
#define DIM  1152
#define NH   16
#define HD   72
#define MTOT (BD * SEQ)                 // 8192
#define QKV_ELEMS (BD * NH * SEQ * HD)  // 9437184
#define OUT_ELEMS (BD * SEQ * DIM)      // 9437184
#define WELEMS (DIM * DIM)              // 1327104
#define PROB_ELEMS ((size_t)BD * NH * SEQ * SEQ)  // 134217728
#define SCALE_F 0.117851130197757931f   // 72^-0.5

// Scratch (allocation-free rule: __device__ globals).  All MMA operands are
// PRE-SPLIT hi/lo bf16.  Q/K/V in [B,H,N,Hd] (head-contiguous — dense rows);
// ctx in [B,N,D] so oproj's A side is a plain [M,DIM] matrix.
__device__ __nv_bfloat16 g_xh[OUT_ELEMS],  g_xl[OUT_ELEMS];    // x
__device__ __nv_bfloat16 g_wh[4][WELEMS],  g_wl[4][WELEMS];    // q,k,v,o weights
__device__ __nv_bfloat16 g_qh[QKV_ELEMS],  g_ql[QKV_ELEMS];    // Q
__device__ __nv_bfloat16 g_kh[QKV_ELEMS],  g_kl[QKV_ELEMS];    // K
__device__ __nv_bfloat16 g_vh[QKV_ELEMS],  g_vl[QKV_ELEMS];    // V
__device__ __nv_bfloat16 g_ch[OUT_ELEMS],  g_cl[OUT_ELEMS];    // ctx
__device__ __nv_bfloat16 g_ph[PROB_ELEMS], g_pl[PROB_ELEMS];   // probs pre-split

// ===========================================================================
// HMMA + cp.async helpers (sm_80+ paths; tcgen05 unavailable on sm_103 base)
// ===========================================================================
__device__ __forceinline__ uint32_t smem_u32(const void* p) {
    uint32_t a;
    asm("{ .reg .u64 t; cvta.to.shared.u64 t, %1; cvt.u32.u64 %0, t; }"
        : "=r"(a) : "l"(p));
    return a;
}
__device__ __forceinline__ void ldsm_x4(uint32_t& r0, uint32_t& r1,
                                        uint32_t& r2, uint32_t& r3, uint32_t a) {
    asm volatile("ldmatrix.sync.aligned.m8n8.x4.shared.b16 {%0,%1,%2,%3}, [%4];"
                 : "=r"(r0), "=r"(r1), "=r"(r2), "=r"(r3) : "r"(a));
}
__device__ __forceinline__ void ldsm_x2(uint32_t& r0, uint32_t& r1, uint32_t a) {
    asm volatile("ldmatrix.sync.aligned.m8n8.x2.shared.b16 {%0,%1}, [%2];"
                 : "=r"(r0), "=r"(r1) : "r"(a));
}
__device__ __forceinline__ void ldsm_x2_trans(uint32_t& r0, uint32_t& r1, uint32_t a) {
    asm volatile("ldmatrix.sync.aligned.m8n8.x2.trans.shared.b16 {%0,%1}, [%2];"
                 : "=r"(r0), "=r"(r1) : "r"(a));
}
__device__ __forceinline__ void mma16816(float* c,
                                         uint32_t a0, uint32_t a1, uint32_t a2, uint32_t a3,
                                         uint32_t b0, uint32_t b1) {
    asm volatile(
        "mma.sync.aligned.m16n8k16.row.col.f32.bf16.bf16.f32 "
        "{%0,%1,%2,%3}, {%4,%5,%6,%7}, {%8,%9}, {%0,%1,%2,%3};"
        : "+f"(c[0]), "+f"(c[1]), "+f"(c[2]), "+f"(c[3])
        : "r"(a0), "r"(a1), "r"(a2), "r"(a3), "r"(b0), "r"(b1));
}
__device__ __forceinline__ void cp16(uint32_t s, const void* g) {
    asm volatile("cp.async.ca.shared.global [%0], [%1], 16;"
                 :: "r"(s), "l"(__cvta_generic_to_global(g)));
}
__device__ __forceinline__ void cp_commit() {
    asm volatile("cp.async.commit_group;");
}
template <int N>
__device__ __forceinline__ void cp_wait() {
    asm volatile("cp.async.wait_group %0;" :: "n"(N));
}

// split fp32x4 -> hi bf16x4 + lo bf16x4 (packed as uint2 each)
__device__ __forceinline__ void split8(uint2& hi, uint2& lo, float4 v) {
    __nv_bfloat162 h01 = __floats2bfloat162_rn(v.x, v.y);
    __nv_bfloat162 h23 = __floats2bfloat162_rn(v.z, v.w);
    float rx = v.x - __bfloat162float(h01.x);
    float ry = v.y - __bfloat162float(h01.y);
    float rz = v.z - __bfloat162float(h23.x);
    float rw = v.w - __bfloat162float(h23.y);
    hi = make_uint2(*(uint32_t*)&h01, *(uint32_t*)&h23);
    __nv_bfloat162 l01 = __floats2bfloat162_rn(rx, ry);
    __nv_bfloat162 l23 = __floats2bfloat162_rn(rz, rw);
    lo = make_uint2(*(uint32_t*)&l01, *(uint32_t*)&l23);
}
__device__ __forceinline__ void split2(uint32_t& hi, uint32_t& lo, float x, float y) {
    __nv_bfloat162 h = __floats2bfloat162_rn(x, y);
    float rx = x - __bfloat162float(h.x);
    float ry = y - __bfloat162float(h.y);
    hi = *(uint32_t*)&h;
    __nv_bfloat162 l = __floats2bfloat162_rn(rx, ry);
    lo = *(uint32_t*)&l;
}

// ===========================================================================
// Kernel 0: pre-split x and the 4 weight matrices (once).
// ===========================================================================
#define X_F4   (OUT_ELEMS / 4)
#define W_F4   (WELEMS / 4)
#define PREP_TOTAL (X_F4 + 4 * W_F4)

__global__ __launch_bounds__(256) void prep_kernel(
    const float* __restrict__ x,
    const float* __restrict__ qw, const float* __restrict__ kw,
    const float* __restrict__ vw, const float* __restrict__ ow)
{
    const size_t i = (size_t)blockIdx.x * 256 + threadIdx.x;
    if (i >= PREP_TOTAL) return;
    const float* src;
    __nv_bfloat16 *dh, *dl;
    size_t e;
    if (i < X_F4) {
        src = x; dh = g_xh; dl = g_xl; e = i;
    } else {
        const size_t wi = i - X_F4;
        const int wsel = (int)(wi / W_F4);
        e = wi % W_F4;
        src = (wsel == 0) ? qw : (wsel == 1) ? kw : (wsel == 2) ? vw : ow;
        dh = g_wh[wsel]; dl = g_wl[wsel];
    }
    float4 v = *(const float4*)(src + e * 4);
    uint2 h, l;
    split8(h, l, v);
    *(uint2*)(dh + e * 4) = h;
    *(uint2*)(dl + e * 4) = l;
}

// ===========================================================================
// Common bf16x3 HMMA GEMM core, cp.async 2-stage pipelined:
//   y[128,128]tile = A[M,K] @ W[N,K]^T ; 36 K-chunks of 32; staging overlaps
//   compute (same structure as the measured 399->257us pv conversion).
// MODE 0: head-scatter epilogue -> hi/lo bf16 [B,H,N,Hd] (qkv)
// MODE 1: plain fp32 [M,DIM] epilogue (o-proj)
// ===========================================================================
#define TSTR 40                           // bf16 per smem row (80B, conflict-free)
#define GT_ARR (128 * TSTR)               // 5120 elems per array
#define GT_STAGE (4 * GT_ARR)             // elems per stage (Ah,Al,Bh,Bl)
#define GT_SMEM_BYTES (2 * GT_STAGE * 2)  // 81920

template <int MODE>
__device__ __forceinline__ void tc_gemm_tile(
    const __nv_bfloat16* __restrict__ Agh, const __nv_bfloat16* __restrict__ Agl,
    const __nv_bfloat16* __restrict__ Wgh, const __nv_bfloat16* __restrict__ Wgl,
    const float* __restrict__ bias,
    float* __restrict__ dst, __nv_bfloat16* __restrict__ dsth,
    __nv_bfloat16* __restrict__ dstl,
    int m0, int n0)
{
    extern __shared__ __nv_bfloat16 gsm[];
    const int tid  = threadIdx.x;
    const int lane = tid & 31;
    const int wid  = tid >> 5;
    const int wm   = (wid >> 2) * 64;
    const int wn   = (wid & 3) * 32;
    const uint32_t sbase = smem_u32(gsm);

    auto issue = [&](int c, int s) {
        const uint32_t st = sbase + (uint32_t)s * (GT_STAGE * 2);
#pragma unroll
        for (int t = 0; t < 2; t++) {
            const int idx = tid + t * 256;           // 0..511
            const int row = idx >> 2;
            const int c8  = (idx & 3) * 8;
            const size_t ga = (size_t)(m0 + row) * DIM + c * 32 + c8;
            const size_t gb = (size_t)(n0 + row) * DIM + c * 32 + c8;
            const uint32_t so = (uint32_t)(row * TSTR + c8) * 2;
            cp16(st + 0 * GT_ARR * 2 + so, Agh + ga);
            cp16(st + 1 * GT_ARR * 2 + so, Agl + ga);
            cp16(st + 2 * GT_ARR * 2 + so, Wgh + gb);
            cp16(st + 3 * GT_ARR * 2 + so, Wgl + gb);
        }
        cp_commit();
    };

    float acc[4][4][4];
#pragma unroll
    for (int i = 0; i < 4; i++)
#pragma unroll
        for (int j = 0; j < 4; j++)
#pragma unroll
            for (int q = 0; q < 4; q++) acc[i][j][q] = 0.f;

    const uint32_t a_off = (wm + (lane & 15)) * (TSTR * 2) + (lane >> 4) * 16;
    const uint32_t b_row_base = wn + (lane & 7);
    const uint32_t b_off = ((lane >> 3) & 1) * 16;

    issue(0, 0);
    issue(1, 1);

    for (int c = 0; c < 36; c++) {
        const int s = c & 1;
        if (c + 1 < 36) cp_wait<1>(); else cp_wait<0>();
        __syncthreads();

        const uint32_t st = sbase + (uint32_t)s * (GT_STAGE * 2);
        const uint32_t ah = st, al = st + GT_ARR * 2;
        const uint32_t bh = st + 2 * GT_ARR * 2, bl = st + 3 * GT_ARR * 2;

#pragma unroll
        for (int ks = 0; ks < 2; ks++) {
            uint32_t Ah[4][4], Al[4][4], Bh[4][2], Bl[4][2];
#pragma unroll
            for (int mf = 0; mf < 4; mf++) {
                const uint32_t addr = a_off + mf * 16 * (TSTR * 2) + ks * 32;
                ldsm_x4(Ah[mf][0], Ah[mf][1], Ah[mf][2], Ah[mf][3], ah + addr);
                ldsm_x4(Al[mf][0], Al[mf][1], Al[mf][2], Al[mf][3], al + addr);
            }
#pragma unroll
            for (int nf = 0; nf < 4; nf++) {
                const uint32_t addr = (b_row_base + nf * 8) * (TSTR * 2) + ks * 32 + b_off;
                ldsm_x2(Bh[nf][0], Bh[nf][1], bh + addr);
                ldsm_x2(Bl[nf][0], Bl[nf][1], bl + addr);
            }
#pragma unroll
            for (int mf = 0; mf < 4; mf++)
#pragma unroll
                for (int nf = 0; nf < 4; nf++) {
                    mma16816(acc[mf][nf], Ah[mf][0], Ah[mf][1], Ah[mf][2], Ah[mf][3],
                             Bh[nf][0], Bh[nf][1]);
                    mma16816(acc[mf][nf], Al[mf][0], Al[mf][1], Al[mf][2], Al[mf][3],
                             Bh[nf][0], Bh[nf][1]);
                    mma16816(acc[mf][nf], Ah[mf][0], Ah[mf][1], Ah[mf][2], Ah[mf][3],
                             Bl[nf][0], Bl[nf][1]);
                }
        }
        __syncthreads();
        if (c + 2 < 36) issue(c + 2, s);
    }

    const int r_base = m0 + wm + (lane >> 2);
    const int c_base = n0 + wn + (lane & 3) * 2;
#pragma unroll
    for (int mf = 0; mf < 4; mf++) {
#pragma unroll
        for (int nf = 0; nf < 4; nf++) {
            const int col = c_base + nf * 8;
            const float bx = bias[col], by = bias[col + 1];
#pragma unroll
            for (int half = 0; half < 2; half++) {
                const int row = r_base + mf * 16 + half * 8;
                const float vx = acc[mf][nf][half * 2 + 0] + bx;
                const float vy = acc[mf][nf][half * 2 + 1] + by;
                if (MODE == 0) {
                    const int bb = row >> 10, n = row & 1023;
                    const int hdh = col / HD, hd = col % HD;
                    const size_t ga = ((size_t)(bb * NH + hdh) * SEQ + n) * HD + hd;
                    uint32_t hi, lo;
                    split2(hi, lo, vx, vy);
                    *(uint32_t*)(dsth + ga) = hi;
                    *(uint32_t*)(dstl + ga) = lo;
                } else {
                    float2 v; v.x = vx; v.y = vy;
                    *(float2*)(dst + (size_t)row * DIM + col) = v;
                }
            }
        }
    }
}

// Kernel 1: QKV projection -> pre-split bf16 head layout [B,H,N,Hd]
__global__ __launch_bounds__(256) void qkv_tc_kernel(
    const float* __restrict__ qb, const float* __restrict__ kb,
    const float* __restrict__ vb)
{
    const int proj = blockIdx.z;
    const float* bias = (proj == 0) ? qb : (proj == 1) ? kb : vb;
    __nv_bfloat16* dh = (proj == 0) ? g_qh : (proj == 1) ? g_kh : g_vh;
    __nv_bfloat16* dl = (proj == 0) ? g_ql : (proj == 1) ? g_kl : g_vl;
    tc_gemm_tile<0>(g_xh, g_xl, g_wh[proj], g_wl[proj], bias,
                    nullptr, dh, dl, blockIdx.y * 128, blockIdx.x * 128);
}

// Kernel 5: O projection (ctx pre-split by pv) -> fp32 out
__global__ __launch_bounds__(256) void oproj_tc_kernel(
    const float* __restrict__ ob, float* __restrict__ out)
{
    tc_gemm_tile<1>(g_ch, g_cl, g_wh[3], g_wl[3], ob,
                    out, nullptr, nullptr, blockIdx.y * 128, blockIdx.x * 128);
}

// ===========================================================================
// Kernel 2: FUSED scores + softmax, register-resident S, Q in SMEM.
//   (unchanged from R13 — measured correct, spill-free)
// ===========================================================================
#define FS_KSTR 88
#define FS_TILE (128 * FS_KSTR)                  // per K array
#define FS_QOFF (4 * FS_TILE)                    // Q tiles after K stages
#define FS_SMEM ((4 * FS_TILE + 2 * 16 * FS_KSTR) * 2)   // 95744 bytes

__global__ __launch_bounds__(256, 2) void fused_scores_softmax_kernel(
    float* __restrict__ probs)
{
    extern __shared__ __nv_bfloat16 ksm[];
    __shared__ float srow[8][16];
    const int tid  = threadIdx.x;
    const int lane = tid & 31;
    const int w    = tid >> 5;
    const int q0   = blockIdx.x * 16;
    const int bhx  = blockIdx.y;

    const __nv_bfloat16* Qgh = g_qh + ((size_t)bhx * SEQ + q0) * HD;
    const __nv_bfloat16* Qgl = g_ql + ((size_t)bhx * SEQ + q0) * HD;
    const __nv_bfloat16* Kgh = g_kh + (size_t)bhx * SEQ * HD;
    const __nv_bfloat16* Kgl = g_kl + (size_t)bhx * SEQ * HD;

    __nv_bfloat16* Qsh = ksm + FS_QOFF;
    __nv_bfloat16* Qsl = Qsh + 16 * FS_KSTR;

    // stage Q (pure copies) + zero Q pads [72,80)
    for (int idx = tid; idx < 16 * 9; idx += 256) {
        const int row = idx / 9;
        const int c8  = (idx % 9) * 8;
        *(uint4*)(Qsh + row * FS_KSTR + c8) =
            *(const uint4*)(Qgh + (size_t)row * HD + c8);
        *(uint4*)(Qsl + row * FS_KSTR + c8) =
            *(const uint4*)(Qgl + (size_t)row * HD + c8);
    }
    for (int i = tid; i < 2 * 16; i += 256) {
        __nv_bfloat16* p = ((i & 1) ? Qsl : Qsh) + (i >> 1) * FS_KSTR + 72;
        *(uint2*)p = make_uint2(0, 0);
        *(uint2*)(p + 4) = make_uint2(0, 0);
    }
    // zero K pads [72,80) of all 4 K arrays
    for (int i = tid; i < 4 * 128; i += 256) {
        __nv_bfloat16* p = ksm + (i >> 7) * FS_TILE + (i & 127) * FS_KSTR + 72;
        *(uint2*)p = make_uint2(0, 0);
        *(uint2*)(p + 4) = make_uint2(0, 0);
    }

    const uint32_t kbase = smem_u32(ksm);
    const uint32_t qh_base = smem_u32(Qsh);
    const uint32_t ql_base = smem_u32(Qsl);

    auto issue = [&](int kb, int s) {
        const uint32_t dh = kbase + (uint32_t)(2 * s) * (FS_TILE * 2);
        const uint32_t dl = dh + FS_TILE * 2;
        for (int idx = tid; idx < 128 * 9; idx += 256) {
            const int row = idx / 9;
            const int c8  = (idx % 9) * 8;
            const size_t ga = (size_t)(kb * 128 + row) * HD + c8;
            const uint32_t so = (uint32_t)(row * FS_KSTR + c8) * 2;
            cp16(dh + so, Kgh + ga);
            cp16(dl + so, Kgl + ga);
        }
        cp_commit();
    };

    issue(0, 0);
    issue(1, 1);

    float acc[8][2][4];
#pragma unroll
    for (int kb = 0; kb < 8; kb++)
#pragma unroll
        for (int nf = 0; nf < 2; nf++)
#pragma unroll
            for (int q = 0; q < 4; q++) acc[kb][nf][q] = 0.f;

    const uint32_t q_off = (lane & 15) * (FS_KSTR * 2) + (lane >> 4) * 16;
    const uint32_t b_row = w * 16 + (lane & 7);
    const uint32_t b_off = ((lane >> 3) & 1) * 16;

#pragma unroll
    for (int kb = 0; kb < 8; kb++) {
        const int s = kb & 1;
        if (kb < 7) cp_wait<1>(); else cp_wait<0>();
        __syncthreads();
        const uint32_t kh = kbase + (uint32_t)(2 * s) * (FS_TILE * 2);
        const uint32_t kl = kh + FS_TILE * 2;
#pragma unroll
        for (int ks = 0; ks < 5; ks++) {
            uint32_t QA[4], QB[4], Bh[2][2], Bl[2][2];
            ldsm_x4(QA[0], QA[1], QA[2], QA[3], qh_base + q_off + ks * 32);
            ldsm_x4(QB[0], QB[1], QB[2], QB[3], ql_base + q_off + ks * 32);
#pragma unroll
            for (int nf = 0; nf < 2; nf++) {
                const uint32_t addr = (b_row + nf * 8) * (FS_KSTR * 2) + ks * 32 + b_off;
                ldsm_x2(Bh[nf][0], Bh[nf][1], kh + addr);
                ldsm_x2(Bl[nf][0], Bl[nf][1], kl + addr);
            }
#pragma unroll
            for (int nf = 0; nf < 2; nf++) {
                mma16816(acc[kb][nf], QA[0], QA[1], QA[2], QA[3], Bh[nf][0], Bh[nf][1]);
                mma16816(acc[kb][nf], QB[0], QB[1], QB[2], QB[3], Bh[nf][0], Bh[nf][1]);
                mma16816(acc[kb][nf], QA[0], QA[1], QA[2], QA[3], Bl[nf][0], Bl[nf][1]);
            }
        }
        __syncthreads();
        if (kb + 2 < 8) issue(kb + 2, s);
    }

    // ---- softmax: exp, quad partial sums, cross-warp reduction ----
    float rs0 = 0.f, rs1 = 0.f;
#pragma unroll
    for (int kb = 0; kb < 8; kb++)
#pragma unroll
        for (int nf = 0; nf < 2; nf++) {
            acc[kb][nf][0] = __expf(acc[kb][nf][0] * SCALE_F);
            acc[kb][nf][1] = __expf(acc[kb][nf][1] * SCALE_F);
            acc[kb][nf][2] = __expf(acc[kb][nf][2] * SCALE_F);
            acc[kb][nf][3] = __expf(acc[kb][nf][3] * SCALE_F);
            rs0 += acc[kb][nf][0] + acc[kb][nf][1];
            rs1 += acc[kb][nf][2] + acc[kb][nf][3];
        }
    rs0 += __shfl_xor_sync(~0u, rs0, 1);
    rs0 += __shfl_xor_sync(~0u, rs0, 2);
    rs1 += __shfl_xor_sync(~0u, rs1, 1);
    rs1 += __shfl_xor_sync(~0u, rs1, 2);

    const int r = lane >> 2;
    if ((lane & 3) == 0) {
        srow[w][r]     = rs0;
        srow[w][r + 8] = rs1;
    }
    __syncthreads();
    float t0 = 0.f, t1 = 0.f;
#pragma unroll
    for (int ww = 0; ww < 8; ww++) {
        t0 += srow[ww][r];
        t1 += srow[ww][r + 8];
    }
    const float inv0 = 1.f / t0;
    const float inv1 = 1.f / t1;

    const size_t rbase0 = (size_t)bhx * SEQ + q0 + r;
    float* p0 = probs + rbase0 * SEQ;
    float* p1 = p0 + 8 * SEQ;
    __nv_bfloat16* ph0 = g_ph + rbase0 * SEQ;
    __nv_bfloat16* ph1 = ph0 + 8 * SEQ;
    __nv_bfloat16* pl0 = g_pl + rbase0 * SEQ;
    __nv_bfloat16* pl1 = pl0 + 8 * SEQ;
#pragma unroll
    for (int kb = 0; kb < 8; kb++)
#pragma unroll
        for (int nf = 0; nf < 2; nf++) {
            const int col = kb * 128 + w * 16 + nf * 8 + (lane & 3) * 2;
            float2 v0, v1;
            v0.x = acc[kb][nf][0] * inv0; v0.y = acc[kb][nf][1] * inv0;
            v1.x = acc[kb][nf][2] * inv1; v1.y = acc[kb][nf][3] * inv1;
            *(float2*)(p0 + col) = v0;
            *(float2*)(p1 + col) = v1;
            uint32_t hi, lo;
            split2(hi, lo, v0.x, v0.y);
            *(uint32_t*)(ph0 + col) = hi;
            *(uint32_t*)(pl0 + col) = lo;
            split2(hi, lo, v1.x, v1.y);
            *(uint32_t*)(ph1 + col) = hi;
            *(uint32_t*)(pl1 + col) = lo;
        }
}

// ===========================================================================
// Kernel 4: PV GEMM, fully cp.async double-buffered (unchanged from R13).
// ===========================================================================
#define PV_STR 72
#define PV_P_ARR (128 * PV_STR)                  // 9216 el
#define PV_V_ARR (64 * PV_STR)                   // 4608 el
#define PV_STAGE (2 * PV_P_ARR + 2 * PV_V_ARR)   // 27648 el
#define PV_SMEM (2 * PV_STAGE * 2)               // 110592 bytes

__global__ __launch_bounds__(256, 2) void pv_tc_kernel()
{
    extern __shared__ __nv_bfloat16 psm[];
    const int tid  = threadIdx.x;
    const int lane = tid & 31;
    const int wid  = tid >> 5;
    const int wm   = (wid >> 2) * 64;
    const int wn   = (wid & 3) * 24;
    const int m0 = blockIdx.x * 128;
    const int bhx = blockIdx.y;
    const int bb = bhx >> 4, hh = bhx & 15;

    const __nv_bfloat16* Pgh = g_ph + (size_t)bhx * SEQ * SEQ;
    const __nv_bfloat16* Pgl = g_pl + (size_t)bhx * SEQ * SEQ;
    const __nv_bfloat16* Vgh = g_vh + (size_t)bhx * SEQ * HD;
    const __nv_bfloat16* Vgl = g_vl + (size_t)bhx * SEQ * HD;

    const uint32_t sbase = smem_u32(psm);

    auto issue = [&](int c, int s) {
        const uint32_t st = sbase + (uint32_t)s * (PV_STAGE * 2);
        const uint32_t ph = st;
        const uint32_t pl = st + PV_P_ARR * 2;
        const uint32_t vh = st + 2 * PV_P_ARR * 2;
        const uint32_t vl = vh + PV_V_ARR * 2;
#pragma unroll
        for (int t = 0; t < 4; t++) {
            const int idx = tid + t * 256;       // 0..1023
            const int row = idx >> 3;
            const int c8  = (idx & 7) * 8;
            const size_t ga = (size_t)(m0 + row) * SEQ + c * 64 + c8;
            const uint32_t so = (uint32_t)(row * PV_STR + c8) * 2;
            cp16(ph + so, Pgh + ga);
            cp16(pl + so, Pgl + ga);
        }
        for (int idx = tid; idx < 64 * 9; idx += 256) {
            const int row = idx / 9;
            const int c8  = (idx % 9) * 8;
            const size_t ga = (size_t)(c * 64 + row) * HD + c8;
            const uint32_t so = (uint32_t)(row * PV_STR + c8) * 2;
            cp16(vh + so, Vgh + ga);
            cp16(vl + so, Vgl + ga);
        }
        cp_commit();
    };

    issue(0, 0);
    issue(1, 1);

    float acc[4][3][4];
#pragma unroll
    for (int i = 0; i < 4; i++)
#pragma unroll
        for (int j = 0; j < 3; j++)
#pragma unroll
            for (int q = 0; q < 4; q++) acc[i][j][q] = 0.f;

    const uint32_t a_off = (wm + (lane & 15)) * (PV_STR * 2) + (lane >> 4) * 16;

    for (int c = 0; c < 16; c++) {
        const int s = c & 1;
        if (c + 1 < 16) cp_wait<1>(); else cp_wait<0>();
        __syncthreads();
        const uint32_t st = sbase + (uint32_t)s * (PV_STAGE * 2);
        const uint32_t ph = st;
        const uint32_t pl = st + PV_P_ARR * 2;
        const uint32_t vh = st + 2 * PV_P_ARR * 2;
        const uint32_t vl = vh + PV_V_ARR * 2;

#pragma unroll
        for (int ks = 0; ks < 4; ks++) {
            uint32_t Ah[4][4], Al[4][4], Bh[3][2], Bl[3][2];
#pragma unroll
            for (int mf = 0; mf < 4; mf++) {
                const uint32_t addr = a_off + mf * 16 * (PV_STR * 2) + ks * 32;
                ldsm_x4(Ah[mf][0], Ah[mf][1], Ah[mf][2], Ah[mf][3], ph + addr);
                ldsm_x4(Al[mf][0], Al[mf][1], Al[mf][2], Al[mf][3], pl + addr);
            }
#pragma unroll
            for (int nf = 0; nf < 3; nf++) {
                if (wn + nf * 8 < HD) {
                    const uint32_t addr = (ks * 16 + (lane & 15)) * (PV_STR * 2)
                                        + (wn + nf * 8) * 2;
                    ldsm_x2_trans(Bh[nf][0], Bh[nf][1], vh + addr);
                    ldsm_x2_trans(Bl[nf][0], Bl[nf][1], vl + addr);
                }
            }
#pragma unroll
            for (int mf = 0; mf < 4; mf++)
#pragma unroll
                for (int nf = 0; nf < 3; nf++) {
                    if (wn + nf * 8 < HD) {
                        mma16816(acc[mf][nf], Ah[mf][0], Ah[mf][1], Ah[mf][2], Ah[mf][3],
                                 Bh[nf][0], Bh[nf][1]);
                        mma16816(acc[mf][nf], Al[mf][0], Al[mf][1], Al[mf][2], Al[mf][3],
                                 Bh[nf][0], Bh[nf][1]);
                        mma16816(acc[mf][nf], Ah[mf][0], Ah[mf][1], Ah[mf][2], Ah[mf][3],
                                 Bl[nf][0], Bl[nf][1]);
                    }
                }
        }
        __syncthreads();
        if (c + 2 < 16) issue(c + 2, s);
    }

    // epilogue: split ctx to hi/lo bf16 [B,N,D] (consumed by oproj)
    const int r_base = m0 + wm + (lane >> 2);
    const int c_base = wn + (lane & 3) * 2;
#pragma unroll
    for (int mf = 0; mf < 4; mf++)
#pragma unroll
        for (int nf = 0; nf < 3; nf++) {
            const int col = c_base + nf * 8;
            if (col < HD) {
#pragma unroll
                for (int half = 0; half < 2; half++) {
                    const int row = r_base + mf * 16 + half * 8;
                    const size_t ga = ((size_t)bb * SEQ + row) * DIM + hh * HD + col;
                    uint32_t hi, lo;
                    split2(hi, lo, acc[mf][nf][half * 2 + 0],
                           acc[mf][nf][half * 2 + 1]);
                    *(uint32_t*)(g_ch + ga) = hi;
                    *(uint32_t*)(g_cl + ga) = lo;
                }
            }
        }
}

// ---------------------------------------------------------------------------
extern "C" void kernel_launch(void* const* d_in, const int* in_sizes, int n_in,
                              void* d_out, int out_size)
{
    const float* x  = (const float*)d_in[0];
    const float* qw = (const float*)d_in[1];
    const float* qb = (const float*)d_in[2];
    const float* kw = (const float*)d_in[3];
    const float* kb = (const float*)d_in[4];
    const float* vw = (const float*)d_in[5];
    const float* vb = (const float*)d_in[6];
    const float* ow = (const float*)d_in[7];
    const float* ob = (const float*)d_in[8];

    float* out   = (float*)d_out;            // [B,N,D]
    float* probs = out + OUT_ELEMS;          // [B,H,N,N]

    cudaFuncSetAttribute(qkv_tc_kernel,
                         cudaFuncAttributeMaxDynamicSharedMemorySize, GT_SMEM_BYTES);
    cudaFuncSetAttribute(oproj_tc_kernel,
                         cudaFuncAttributeMaxDynamicSharedMemorySize, GT_SMEM_BYTES);
    cudaFuncSetAttribute(fused_scores_softmax_kernel,
                         cudaFuncAttributeMaxDynamicSharedMemorySize, FS_SMEM);
    cudaFuncSetAttribute(pv_tc_kernel,
                         cudaFuncAttributeMaxDynamicSharedMemorySize, PV_SMEM);

    prep_kernel<<<(PREP_TOTAL + 255) / 256, 256>>>(x, qw, kw, vw, ow);

    dim3 gq(DIM / 128, MTOT / 128, 3);       // (9, 64, 3)
    qkv_tc_kernel<<<gq, 256, GT_SMEM_BYTES>>>(qb, kb, vb);

    dim3 gs(SEQ / 16, BD * NH);              // (64, 128)
    fused_scores_softmax_kernel<<<gs, 256, FS_SMEM>>>(probs);

    dim3 gp(SEQ / 128, BD * NH);             // (8, 128)
    pv_tc_kernel<<<gp, 256, PV_SMEM>>>();

    dim3 go(DIM / 128, MTOT / 128);          // (9, 64)
    oproj_tc_kernel<<<go, 256, GT_SMEM_BYTES>>>(ob, out);
}

// round 15
// speedup vs baseline: 1.6160x; 1.0550x over previous
#include <cuda_runtime.h>
#include <cuda_bf16.h>
#include <cstdint>
#include <math.h>

// ---------------------------------------------------------------------------
// SiglipAttention: B=8, N=1024, D=1152, H=16, Hd=72
// Outputs (concatenated in d_out): out [B,N,D] fp32, attn_probs [B,H,N,N] fp32
// ---------------------------------------------------------------------------

#define BD   8
#define SEQ  1024
#define DIM  1152
#define NH   16
#define HD   72
#define MTOT (BD * SEQ)                 // 8192
#define QKV_ELEMS (BD * NH * SEQ * HD)  // 9437184
#define OUT_ELEMS (BD * SEQ * DIM)      // 9437184
#define WELEMS (DIM * DIM)              // 1327104
#define SCALE_F 0.117851130197757931f   // 72^-0.5

// Scratch (allocation-free rule: __device__ globals).  All MMA operands are
// PRE-SPLIT hi/lo bf16.  Q/K/V in [B,H,N,Hd]; ctx in [B,N,D].
__device__ __nv_bfloat16 g_xh[OUT_ELEMS],  g_xl[OUT_ELEMS];    // x
__device__ __nv_bfloat16 g_wh[4][WELEMS],  g_wl[4][WELEMS];    // q,k,v,o weights
__device__ __nv_bfloat16 g_qh[QKV_ELEMS],  g_ql[QKV_ELEMS];    // Q
__device__ __nv_bfloat16 g_kh[QKV_ELEMS],  g_kl[QKV_ELEMS];    // K
__device__ __nv_bfloat16 g_vh[QKV_ELEMS],  g_vl[QKV_ELEMS];    // V
__device__ __nv_bfloat16 g_ch[OUT_ELEMS],  g_cl[OUT_ELEMS];    // ctx

// ===========================================================================
// HMMA + cp.async helpers (sm_80+ paths; tcgen05 unavailable on sm_103 base)
// ===========================================================================
__device__ __forceinline__ uint32_t smem_u32(const void* p) {
    uint32_t a;
    asm("{ .reg .u64 t; cvta.to.shared.u64 t, %1; cvt.u32.u64 %0, t; }"
        : "=r"(a) : "l"(p));
    return a;
}
__device__ __forceinline__ void ldsm_x4(uint32_t& r0, uint32_t& r1,
                                        uint32_t& r2, uint32_t& r3, uint32_t a) {
    asm volatile("ldmatrix.sync.aligned.m8n8.x4.shared.b16 {%0,%1,%2,%3}, [%4];"
                 : "=r"(r0), "=r"(r1), "=r"(r2), "=r"(r3) : "r"(a));
}
__device__ __forceinline__ void ldsm_x2(uint32_t& r0, uint32_t& r1, uint32_t a) {
    asm volatile("ldmatrix.sync.aligned.m8n8.x2.shared.b16 {%0,%1}, [%2];"
                 : "=r"(r0), "=r"(r1) : "r"(a));
}
__device__ __forceinline__ void ldsm_x2_trans(uint32_t& r0, uint32_t& r1, uint32_t a) {
    asm volatile("ldmatrix.sync.aligned.m8n8.x2.trans.shared.b16 {%0,%1}, [%2];"
                 : "=r"(r0), "=r"(r1) : "r"(a));
}
__device__ __forceinline__ void mma16816(float* c,
                                         uint32_t a0, uint32_t a1, uint32_t a2, uint32_t a3,
                                         uint32_t b0, uint32_t b1) {
    asm volatile(
        "mma.sync.aligned.m16n8k16.row.col.f32.bf16.bf16.f32 "
        "{%0,%1,%2,%3}, {%4,%5,%6,%7}, {%8,%9}, {%0,%1,%2,%3};"
        : "+f"(c[0]), "+f"(c[1]), "+f"(c[2]), "+f"(c[3])
        : "r"(a0), "r"(a1), "r"(a2), "r"(a3), "r"(b0), "r"(b1));
}
__device__ __forceinline__ void cp16(uint32_t s, const void* g) {
    asm volatile("cp.async.ca.shared.global [%0], [%1], 16;"
                 :: "r"(s), "l"(__cvta_generic_to_global(g)));
}
__device__ __forceinline__ void cp_commit() {
    asm volatile("cp.async.commit_group;");
}
template <int N>
__device__ __forceinline__ void cp_wait() {
    asm volatile("cp.async.wait_group %0;" :: "n"(N));
}

// split fp32x4 -> hi bf16x4 + lo bf16x4 (packed as uint2 each)
__device__ __forceinline__ void split8(uint2& hi, uint2& lo, float4 v) {
    __nv_bfloat162 h01 = __floats2bfloat162_rn(v.x, v.y);
    __nv_bfloat162 h23 = __floats2bfloat162_rn(v.z, v.w);
    float rx = v.x - __bfloat162float(h01.x);
    float ry = v.y - __bfloat162float(h01.y);
    float rz = v.z - __bfloat162float(h23.x);
    float rw = v.w - __bfloat162float(h23.y);
    hi = make_uint2(*(uint32_t*)&h01, *(uint32_t*)&h23);
    __nv_bfloat162 l01 = __floats2bfloat162_rn(rx, ry);
    __nv_bfloat162 l23 = __floats2bfloat162_rn(rz, rw);
    lo = make_uint2(*(uint32_t*)&l01, *(uint32_t*)&l23);
}
__device__ __forceinline__ void split2(uint32_t& hi, uint32_t& lo, float x, float y) {
    __nv_bfloat162 h = __floats2bfloat162_rn(x, y);
    float rx = x - __bfloat162float(h.x);
    float ry = y - __bfloat162float(h.y);
    hi = *(uint32_t*)&h;
    __nv_bfloat162 l = __floats2bfloat162_rn(rx, ry);
    lo = *(uint32_t*)&l;
}

// ===========================================================================
// Kernel 0: pre-split x and the 4 weight matrices (once).
// ===========================================================================
#define X_F4   (OUT_ELEMS / 4)
#define W_F4   (WELEMS / 4)
#define PREP_TOTAL (X_F4 + 4 * W_F4)

__global__ __launch_bounds__(256) void prep_kernel(
    const float* __restrict__ x,
    const float* __restrict__ qw, const float* __restrict__ kw,
    const float* __restrict__ vw, const float* __restrict__ ow)
{
    const size_t i = (size_t)blockIdx.x * 256 + threadIdx.x;
    if (i >= PREP_TOTAL) return;
    const float* src;
    __nv_bfloat16 *dh, *dl;
    size_t e;
    if (i < X_F4) {
        src = x; dh = g_xh; dl = g_xl; e = i;
    } else {
        const size_t wi = i - X_F4;
        const int wsel = (int)(wi / W_F4);
        e = wi % W_F4;
        src = (wsel == 0) ? qw : (wsel == 1) ? kw : (wsel == 2) ? vw : ow;
        dh = g_wh[wsel]; dl = g_wl[wsel];
    }
    float4 v = *(const float4*)(src + e * 4);
    uint2 h, l;
    split8(h, l, v);
    *(uint2*)(dh + e * 4) = h;
    *(uint2*)(dl + e * 4) = l;
}

// ===========================================================================
// Common bf16x3 HMMA GEMM core, cp.async 2-stage pipelined (R14-proven).
// MODE 0: head-scatter epilogue -> hi/lo bf16 [B,H,N,Hd] (qkv)
// MODE 1: plain fp32 [M,DIM] epilogue (o-proj)
// ===========================================================================
#define TSTR 40                           // bf16 per smem row (80B, conflict-free)
#define GT_ARR (128 * TSTR)               // 5120 elems per array
#define GT_STAGE (4 * GT_ARR)             // elems per stage (Ah,Al,Bh,Bl)
#define GT_SMEM_BYTES (2 * GT_STAGE * 2)  // 81920

template <int MODE>
__device__ __forceinline__ void tc_gemm_tile(
    const __nv_bfloat16* __restrict__ Agh, const __nv_bfloat16* __restrict__ Agl,
    const __nv_bfloat16* __restrict__ Wgh, const __nv_bfloat16* __restrict__ Wgl,
    const float* __restrict__ bias,
    float* __restrict__ dst, __nv_bfloat16* __restrict__ dsth,
    __nv_bfloat16* __restrict__ dstl,
    int m0, int n0)
{
    extern __shared__ __nv_bfloat16 gsm[];
    const int tid  = threadIdx.x;
    const int lane = tid & 31;
    const int wid  = tid >> 5;
    const int wm   = (wid >> 2) * 64;
    const int wn   = (wid & 3) * 32;
    const uint32_t sbase = smem_u32(gsm);

    auto issue = [&](int c, int s) {
        const uint32_t st = sbase + (uint32_t)s * (GT_STAGE * 2);
#pragma unroll
        for (int t = 0; t < 2; t++) {
            const int idx = tid + t * 256;           // 0..511
            const int row = idx >> 2;
            const int c8  = (idx & 3) * 8;
            const size_t ga = (size_t)(m0 + row) * DIM + c * 32 + c8;
            const size_t gb = (size_t)(n0 + row) * DIM + c * 32 + c8;
            const uint32_t so = (uint32_t)(row * TSTR + c8) * 2;
            cp16(st + 0 * GT_ARR * 2 + so, Agh + ga);
            cp16(st + 1 * GT_ARR * 2 + so, Agl + ga);
            cp16(st + 2 * GT_ARR * 2 + so, Wgh + gb);
            cp16(st + 3 * GT_ARR * 2 + so, Wgl + gb);
        }
        cp_commit();
    };

    float acc[4][4][4];
#pragma unroll
    for (int i = 0; i < 4; i++)
#pragma unroll
        for (int j = 0; j < 4; j++)
#pragma unroll
            for (int q = 0; q < 4; q++) acc[i][j][q] = 0.f;

    const uint32_t a_off = (wm + (lane & 15)) * (TSTR * 2) + (lane >> 4) * 16;
    const uint32_t b_row_base = wn + (lane & 7);
    const uint32_t b_off = ((lane >> 3) & 1) * 16;

    issue(0, 0);
    issue(1, 1);

    for (int c = 0; c < 36; c++) {
        const int s = c & 1;
        if (c + 1 < 36) cp_wait<1>(); else cp_wait<0>();
        __syncthreads();

        const uint32_t st = sbase + (uint32_t)s * (GT_STAGE * 2);
        const uint32_t ah = st, al = st + GT_ARR * 2;
        const uint32_t bh = st + 2 * GT_ARR * 2, bl = st + 3 * GT_ARR * 2;

#pragma unroll
        for (int ks = 0; ks < 2; ks++) {
            uint32_t Ah[4][4], Al[4][4], Bh[4][2], Bl[4][2];
#pragma unroll
            for (int mf = 0; mf < 4; mf++) {
                const uint32_t addr = a_off + mf * 16 * (TSTR * 2) + ks * 32;
                ldsm_x4(Ah[mf][0], Ah[mf][1], Ah[mf][2], Ah[mf][3], ah + addr);
                ldsm_x4(Al[mf][0], Al[mf][1], Al[mf][2], Al[mf][3], al + addr);
            }
#pragma unroll
            for (int nf = 0; nf < 4; nf++) {
                const uint32_t addr = (b_row_base + nf * 8) * (TSTR * 2) + ks * 32 + b_off;
                ldsm_x2(Bh[nf][0], Bh[nf][1], bh + addr);
                ldsm_x2(Bl[nf][0], Bl[nf][1], bl + addr);
            }
#pragma unroll
            for (int mf = 0; mf < 4; mf++)
#pragma unroll
                for (int nf = 0; nf < 4; nf++) {
                    mma16816(acc[mf][nf], Ah[mf][0], Ah[mf][1], Ah[mf][2], Ah[mf][3],
                             Bh[nf][0], Bh[nf][1]);
                    mma16816(acc[mf][nf], Al[mf][0], Al[mf][1], Al[mf][2], Al[mf][3],
                             Bh[nf][0], Bh[nf][1]);
                    mma16816(acc[mf][nf], Ah[mf][0], Ah[mf][1], Ah[mf][2], Ah[mf][3],
                             Bl[nf][0], Bl[nf][1]);
                }
        }
        __syncthreads();
        if (c + 2 < 36) issue(c + 2, s);
    }

    const int r_base = m0 + wm + (lane >> 2);
    const int c_base = n0 + wn + (lane & 3) * 2;
#pragma unroll
    for (int mf = 0; mf < 4; mf++) {
#pragma unroll
        for (int nf = 0; nf < 4; nf++) {
            const int col = c_base + nf * 8;
            const float bx = bias[col], by = bias[col + 1];
#pragma unroll
            for (int half = 0; half < 2; half++) {
                const int row = r_base + mf * 16 + half * 8;
                const float vx = acc[mf][nf][half * 2 + 0] + bx;
                const float vy = acc[mf][nf][half * 2 + 1] + by;
                if (MODE == 0) {
                    const int bb = row >> 10, n = row & 1023;
                    const int hdh = col / HD, hd = col % HD;
                    const size_t ga = ((size_t)(bb * NH + hdh) * SEQ + n) * HD + hd;
                    uint32_t hi, lo;
                    split2(hi, lo, vx, vy);
                    *(uint32_t*)(dsth + ga) = hi;
                    *(uint32_t*)(dstl + ga) = lo;
                } else {
                    float2 v; v.x = vx; v.y = vy;
                    *(float2*)(dst + (size_t)row * DIM + col) = v;
                }
            }
        }
    }
}

// Kernel 1: QKV projection -> pre-split bf16 head layout [B,H,N,Hd]
__global__ __launch_bounds__(256) void qkv_tc_kernel(
    const float* __restrict__ qb, const float* __restrict__ kb,
    const float* __restrict__ vb)
{
    const int proj = blockIdx.z;
    const float* bias = (proj == 0) ? qb : (proj == 1) ? kb : vb;
    __nv_bfloat16* dh = (proj == 0) ? g_qh : (proj == 1) ? g_kh : g_vh;
    __nv_bfloat16* dl = (proj == 0) ? g_ql : (proj == 1) ? g_kl : g_vl;
    tc_gemm_tile<0>(g_xh, g_xl, g_wh[proj], g_wl[proj], bias,
                    nullptr, dh, dl, blockIdx.y * 128, blockIdx.x * 128);
}

// Kernel 4: O projection (ctx pre-split by attention) -> fp32 out
__global__ __launch_bounds__(256) void oproj_tc_kernel(
    const float* __restrict__ ob, float* __restrict__ out)
{
    tc_gemm_tile<1>(g_ch, g_cl, g_wh[3], g_wl[3], ob,
                    out, nullptr, nullptr, blockIdx.y * 128, blockIdx.x * 128);
}

// ===========================================================================
// Kernel 2: FULLY FUSED attention: scores + softmax + PV.
//   16 q-rows x 1024 keys per CTA.  Phase 1: S = scale*Q@K^T in registers
//   (K cp.async double-buffered).  Phase 2: no-max softmax (quad + cross-warp
//   sums), normalize in regs, write probs fp32.  Phase 3: each warp's
//   normalized S C-frags repack directly into A-frags (hi/lo bf16) for
//   PV m16k16 MMAs over its own 16 keys/tile; V staged through the same
//   double buffer, fed via ldmatrix.trans (pv-proven path).  Partial ctx
//   per warp reduced 8-way through smem -> hi/lo bf16 ctx [B,N,D].
// ===========================================================================
#define FS_KSTR 88
#define FS_TILE (128 * FS_KSTR)                  // per array (K or V tile)
#define FS_QOFF (4 * FS_TILE)                    // Q tiles after the 2 stages
#define FS_SMEM ((4 * FS_TILE + 2 * 16 * FS_KSTR) * 2)   // 95744 bytes
#define CTX_STR 76                               // fp32 ctx partial row stride

__global__ __launch_bounds__(256, 2) void fused_attn_kernel(
    float* __restrict__ probs)
{
    extern __shared__ __nv_bfloat16 ksm[];
    __shared__ float srow[8][16];
    const int tid  = threadIdx.x;
    const int lane = tid & 31;
    const int w    = tid >> 5;
    const int q0   = blockIdx.x * 16;
    const int bhx  = blockIdx.y;
    const int bb   = bhx >> 4, hh = bhx & 15;

    const __nv_bfloat16* Qgh = g_qh + ((size_t)bhx * SEQ + q0) * HD;
    const __nv_bfloat16* Qgl = g_ql + ((size_t)bhx * SEQ + q0) * HD;
    const __nv_bfloat16* Kgh = g_kh + (size_t)bhx * SEQ * HD;
    const __nv_bfloat16* Kgl = g_kl + (size_t)bhx * SEQ * HD;
    const __nv_bfloat16* Vgh = g_vh + (size_t)bhx * SEQ * HD;
    const __nv_bfloat16* Vgl = g_vl + (size_t)bhx * SEQ * HD;

    __nv_bfloat16* Qsh = ksm + FS_QOFF;
    __nv_bfloat16* Qsl = Qsh + 16 * FS_KSTR;

    // stage Q (pure copies) + zero Q pads [72,80)
    for (int idx = tid; idx < 16 * 9; idx += 256) {
        const int row = idx / 9;
        const int c8  = (idx % 9) * 8;
        *(uint4*)(Qsh + row * FS_KSTR + c8) =
            *(const uint4*)(Qgh + (size_t)row * HD + c8);
        *(uint4*)(Qsl + row * FS_KSTR + c8) =
            *(const uint4*)(Qgl + (size_t)row * HD + c8);
    }
    for (int i = tid; i < 2 * 16; i += 256) {
        __nv_bfloat16* p = ((i & 1) ? Qsl : Qsh) + (i >> 1) * FS_KSTR + 72;
        *(uint2*)p = make_uint2(0, 0);
        *(uint2*)(p + 4) = make_uint2(0, 0);
    }
    // zero pads [72,80) of all 4 stage arrays (K phase needs them zero)
    for (int i = tid; i < 4 * 128; i += 256) {
        __nv_bfloat16* p = ksm + (i >> 7) * FS_TILE + (i & 127) * FS_KSTR + 72;
        *(uint2*)p = make_uint2(0, 0);
        *(uint2*)(p + 4) = make_uint2(0, 0);
    }

    const uint32_t kbase = smem_u32(ksm);
    const uint32_t qh_base = smem_u32(Qsh);
    const uint32_t ql_base = smem_u32(Qsl);

    // stage a 128x72 tile (K or V) into stage s: pure cp.async copies
    auto issue = [&](const __nv_bfloat16* Gh, const __nv_bfloat16* Gl,
                     int tile, int s) {
        const uint32_t dh = kbase + (uint32_t)(2 * s) * (FS_TILE * 2);
        const uint32_t dl = dh + FS_TILE * 2;
        for (int idx = tid; idx < 128 * 9; idx += 256) {
            const int row = idx / 9;
            const int c8  = (idx % 9) * 8;
            const size_t ga = (size_t)(tile * 128 + row) * HD + c8;
            const uint32_t so = (uint32_t)(row * FS_KSTR + c8) * 2;
            cp16(dh + so, Gh + ga);
            cp16(dl + so, Gl + ga);
        }
        cp_commit();
    };

    issue(Kgh, Kgl, 0, 0);
    issue(Kgh, Kgl, 1, 1);

    float acc[8][2][4];
#pragma unroll
    for (int kb = 0; kb < 8; kb++)
#pragma unroll
        for (int nf = 0; nf < 2; nf++)
#pragma unroll
            for (int q = 0; q < 4; q++) acc[kb][nf][q] = 0.f;

    const uint32_t q_off = (lane & 15) * (FS_KSTR * 2) + (lane >> 4) * 16;
    const uint32_t b_row = w * 16 + (lane & 7);
    const uint32_t b_off = ((lane >> 3) & 1) * 16;

    // ---- Phase 1: scores ----
#pragma unroll
    for (int kb = 0; kb < 8; kb++) {
        const int s = kb & 1;
        if (kb < 7) cp_wait<1>(); else cp_wait<0>();
        __syncthreads();
        const uint32_t kh = kbase + (uint32_t)(2 * s) * (FS_TILE * 2);
        const uint32_t kl = kh + FS_TILE * 2;
#pragma unroll
        for (int ks = 0; ks < 5; ks++) {
            uint32_t QA[4], QB[4], Bh[2][2], Bl[2][2];
            ldsm_x4(QA[0], QA[1], QA[2], QA[3], qh_base + q_off + ks * 32);
            ldsm_x4(QB[0], QB[1], QB[2], QB[3], ql_base + q_off + ks * 32);
#pragma unroll
            for (int nf = 0; nf < 2; nf++) {
                const uint32_t addr = (b_row + nf * 8) * (FS_KSTR * 2) + ks * 32 + b_off;
                ldsm_x2(Bh[nf][0], Bh[nf][1], kh + addr);
                ldsm_x2(Bl[nf][0], Bl[nf][1], kl + addr);
            }
#pragma unroll
            for (int nf = 0; nf < 2; nf++) {
                mma16816(acc[kb][nf], QA[0], QA[1], QA[2], QA[3], Bh[nf][0], Bh[nf][1]);
                mma16816(acc[kb][nf], QB[0], QB[1], QB[2], QB[3], Bh[nf][0], Bh[nf][1]);
                mma16816(acc[kb][nf], QA[0], QA[1], QA[2], QA[3], Bl[nf][0], Bl[nf][1]);
            }
        }
        __syncthreads();
        if (kb + 2 < 8) issue(Kgh, Kgl, kb + 2, s);
    }

    // start V loads immediately (overlap with softmax + probs writes)
    issue(Vgh, Vgl, 0, 0);
    issue(Vgh, Vgl, 1, 1);

    // ---- Phase 2: softmax (no max pass; exact shift-invariance) ----
    float rs0 = 0.f, rs1 = 0.f;
#pragma unroll
    for (int kb = 0; kb < 8; kb++)
#pragma unroll
        for (int nf = 0; nf < 2; nf++) {
            acc[kb][nf][0] = __expf(acc[kb][nf][0] * SCALE_F);
            acc[kb][nf][1] = __expf(acc[kb][nf][1] * SCALE_F);
            acc[kb][nf][2] = __expf(acc[kb][nf][2] * SCALE_F);
            acc[kb][nf][3] = __expf(acc[kb][nf][3] * SCALE_F);
            rs0 += acc[kb][nf][0] + acc[kb][nf][1];
            rs1 += acc[kb][nf][2] + acc[kb][nf][3];
        }
    rs0 += __shfl_xor_sync(~0u, rs0, 1);
    rs0 += __shfl_xor_sync(~0u, rs0, 2);
    rs1 += __shfl_xor_sync(~0u, rs1, 1);
    rs1 += __shfl_xor_sync(~0u, rs1, 2);

    const int r = lane >> 2;
    if ((lane & 3) == 0) {
        srow[w][r]     = rs0;
        srow[w][r + 8] = rs1;
    }
    __syncthreads();
    float t0 = 0.f, t1 = 0.f;
#pragma unroll
    for (int ww = 0; ww < 8; ww++) {
        t0 += srow[ww][r];
        t1 += srow[ww][r + 8];
    }
    const float inv0 = 1.f / t0;
    const float inv1 = 1.f / t1;

    // normalize S in regs; write probs fp32 (final output)
    const size_t rbase0 = (size_t)bhx * SEQ + q0 + r;
    float* p0 = probs + rbase0 * SEQ;
    float* p1 = p0 + 8 * SEQ;
#pragma unroll
    for (int kb = 0; kb < 8; kb++)
#pragma unroll
        for (int nf = 0; nf < 2; nf++) {
            acc[kb][nf][0] *= inv0; acc[kb][nf][1] *= inv0;
            acc[kb][nf][2] *= inv1; acc[kb][nf][3] *= inv1;
            const int col = kb * 128 + w * 16 + nf * 8 + (lane & 3) * 2;
            float2 v0, v1;
            v0.x = acc[kb][nf][0]; v0.y = acc[kb][nf][1];
            v1.x = acc[kb][nf][2]; v1.y = acc[kb][nf][3];
            *(float2*)(p0 + col) = v0;
            *(float2*)(p1 + col) = v1;
        }

    // ---- Phase 3: PV.  Each warp: its S frags (16 keys per tile) as A;
    //      V tile rows via ldmatrix.trans as B.  Partial ctx per warp. ----
    float cacc[9][4];
#pragma unroll
    for (int nf2 = 0; nf2 < 9; nf2++)
#pragma unroll
        for (int q = 0; q < 4; q++) cacc[nf2][q] = 0.f;

    const uint32_t v_row_addr = (uint32_t)(w * 16 + (lane & 15)) * (FS_KSTR * 2);

#pragma unroll
    for (int vb = 0; vb < 8; vb++) {
        const int s = vb & 1;
        if (vb < 7) cp_wait<1>(); else cp_wait<0>();
        __syncthreads();
        const uint32_t vh = kbase + (uint32_t)(2 * s) * (FS_TILE * 2);
        const uint32_t vl = vh + FS_TILE * 2;

        // repack this warp's S C-frags -> A m16k16 frags (hi/lo bf16)
        uint32_t Ah[4], Al[4];
        split2(Ah[0], Al[0], acc[vb][0][0], acc[vb][0][1]);  // (r,   c..c+1)
        split2(Ah[1], Al[1], acc[vb][0][2], acc[vb][0][3]);  // (r+8, c..c+1)
        split2(Ah[2], Al[2], acc[vb][1][0], acc[vb][1][1]);  // (r,   c+8..)
        split2(Ah[3], Al[3], acc[vb][1][2], acc[vb][1][3]);  // (r+8, c+8..)

#pragma unroll
        for (int nf2 = 0; nf2 < 9; nf2++) {
            uint32_t Bh0, Bh1, Bl0, Bl1;
            const uint32_t addr = v_row_addr + nf2 * 8 * 2;
            ldsm_x2_trans(Bh0, Bh1, vh + addr);
            ldsm_x2_trans(Bl0, Bl1, vl + addr);
            mma16816(cacc[nf2], Ah[0], Ah[1], Ah[2], Ah[3], Bh0, Bh1);
            mma16816(cacc[nf2], Al[0], Al[1], Al[2], Al[3], Bh0, Bh1);
            mma16816(cacc[nf2], Ah[0], Ah[1], Ah[2], Ah[3], Bl0, Bl1);
        }
        __syncthreads();
        if (vb + 2 < 8) issue(Vgh, Vgl, vb + 2, s);
    }

    // ---- 8-way cross-warp ctx reduction through smem (reuse stage area) ----
    __syncthreads();                      // V stages dead; overlay sctx
    float* sctx = (float*)ksm;            // [8 warps][16 rows][CTX_STR]
    {
        const int cb = (lane & 3) * 2;
        float* base = sctx + w * (16 * CTX_STR);
#pragma unroll
        for (int nf2 = 0; nf2 < 9; nf2++) {
            const int col = nf2 * 8 + cb;
            *(float2*)(base + r * CTX_STR + col) =
                make_float2(cacc[nf2][0], cacc[nf2][1]);
            *(float2*)(base + (r + 8) * CTX_STR + col) =
                make_float2(cacc[nf2][2], cacc[nf2][3]);
        }
    }
    __syncthreads();

    // sum 8 warp slots, split to hi/lo bf16, store ctx [B,N,D]
    for (int p = tid; p < 16 * 36; p += 256) {
        const int row = p / 36;
        const int c2  = (p % 36) * 2;
        float sx = 0.f, sy = 0.f;
#pragma unroll
        for (int ww = 0; ww < 8; ww++) {
            const float* b = sctx + ww * (16 * CTX_STR) + row * CTX_STR + c2;
            sx += b[0];
            sy += b[1];
        }
        const size_t ga = ((size_t)bb * SEQ + q0 + row) * DIM + hh * HD + c2;
        uint32_t hi, lo;
        split2(hi, lo, sx, sy);
        *(uint32_t*)(g_ch + ga) = hi;
        *(uint32_t*)(g_cl + ga) = lo;
    }
}

// ---------------------------------------------------------------------------
extern "C" void kernel_launch(void* const* d_in, const int* in_sizes, int n_in,
                              void* d_out, int out_size)
{
    const float* x  = (const float*)d_in[0];
    const float* qw = (const float*)d_in[1];
    const float* qb = (const float*)d_in[2];
    const float* kw = (const float*)d_in[3];
    const float* kb = (const float*)d_in[4];
    const float* vw = (const float*)d_in[5];
    const float* vb = (const float*)d_in[6];
    const float* ow = (const float*)d_in[7];
    const float* ob = (const float*)d_in[8];

    float* out   = (float*)d_out;            // [B,N,D]
    float* probs = out + OUT_ELEMS;          // [B,H,N,N]

    cudaFuncSetAttribute(qkv_tc_kernel,
                         cudaFuncAttributeMaxDynamicSharedMemorySize, GT_SMEM_BYTES);
    cudaFuncSetAttribute(oproj_tc_kernel,
                         cudaFuncAttributeMaxDynamicSharedMemorySize, GT_SMEM_BYTES);
    cudaFuncSetAttribute(fused_attn_kernel,
                         cudaFuncAttributeMaxDynamicSharedMemorySize, FS_SMEM);

    prep_kernel<<<(PREP_TOTAL + 255) / 256, 256>>>(x, qw, kw, vw, ow);

    dim3 gq(DIM / 128, MTOT / 128, 3);       // (9, 64, 3)
    qkv_tc_kernel<<<gq, 256, GT_SMEM_BYTES>>>(qb, kb, vb);

    dim3 gs(SEQ / 16, BD * NH);              // (64, 128)
    fused_attn_kernel<<<gs, 256, FS_SMEM>>>(probs);

    dim3 go(DIM / 128, MTOT / 128);          // (9, 64)
    oproj_tc_kernel<<<go, 256, GT_SMEM_BYTES>>>(ob, out);
}

// round 16
// speedup vs baseline: 1.7381x; 1.0756x over previous
#include <cuda_runtime.h>
#include <cuda_bf16.h>
#include <cstdint>
#include <math.h>

// ---------------------------------------------------------------------------
// SiglipAttention: B=8, N=1024, D=1152, H=16, Hd=72
// Outputs (concatenated in d_out): out [B,N,D] fp32, attn_probs [B,H,N,N] fp32
// ---------------------------------------------------------------------------

#define BD   8
#define SEQ  1024
#define DIM  1152
#define NH   16
#define HD   72
#define MTOT (BD * SEQ)                 // 8192
#define QKV_ELEMS (BD * NH * SEQ * HD)  // 9437184
#define OUT_ELEMS (BD * SEQ * DIM)      // 9437184
#define WELEMS (DIM * DIM)              // 1327104
#define SCALE_F 0.117851130197757931f   // 72^-0.5

// Scratch (allocation-free rule: __device__ globals).  All MMA operands are
// PRE-SPLIT hi/lo bf16.  Q/K/V in [B,H,N,Hd]; ctx in [B,N,D].
__device__ __nv_bfloat16 g_xh[OUT_ELEMS],  g_xl[OUT_ELEMS];    // x
__device__ __nv_bfloat16 g_wh[4][WELEMS],  g_wl[4][WELEMS];    // q,k,v,o weights
__device__ __nv_bfloat16 g_qh[QKV_ELEMS],  g_ql[QKV_ELEMS];    // Q
__device__ __nv_bfloat16 g_kh[QKV_ELEMS],  g_kl[QKV_ELEMS];    // K
__device__ __nv_bfloat16 g_vh[QKV_ELEMS],  g_vl[QKV_ELEMS];    // V
__device__ __nv_bfloat16 g_ch[OUT_ELEMS],  g_cl[OUT_ELEMS];    // ctx

// ===========================================================================
// HMMA + cp.async helpers (sm_80+ paths; tcgen05 unavailable on sm_103 base)
// ===========================================================================
__device__ __forceinline__ uint32_t smem_u32(const void* p) {
    uint32_t a;
    asm("{ .reg .u64 t; cvta.to.shared.u64 t, %1; cvt.u32.u64 %0, t; }"
        : "=r"(a) : "l"(p));
    return a;
}
__device__ __forceinline__ void ldsm_x4(uint32_t& r0, uint32_t& r1,
                                        uint32_t& r2, uint32_t& r3, uint32_t a) {
    asm volatile("ldmatrix.sync.aligned.m8n8.x4.shared.b16 {%0,%1,%2,%3}, [%4];"
                 : "=r"(r0), "=r"(r1), "=r"(r2), "=r"(r3) : "r"(a));
}
__device__ __forceinline__ void ldsm_x2(uint32_t& r0, uint32_t& r1, uint32_t a) {
    asm volatile("ldmatrix.sync.aligned.m8n8.x2.shared.b16 {%0,%1}, [%2];"
                 : "=r"(r0), "=r"(r1) : "r"(a));
}
__device__ __forceinline__ void ldsm_x2_trans(uint32_t& r0, uint32_t& r1, uint32_t a) {
    asm volatile("ldmatrix.sync.aligned.m8n8.x2.trans.shared.b16 {%0,%1}, [%2];"
                 : "=r"(r0), "=r"(r1) : "r"(a));
}
__device__ __forceinline__ void mma16816(float* c,
                                         uint32_t a0, uint32_t a1, uint32_t a2, uint32_t a3,
                                         uint32_t b0, uint32_t b1) {
    asm volatile(
        "mma.sync.aligned.m16n8k16.row.col.f32.bf16.bf16.f32 "
        "{%0,%1,%2,%3}, {%4,%5,%6,%7}, {%8,%9}, {%0,%1,%2,%3};"
        : "+f"(c[0]), "+f"(c[1]), "+f"(c[2]), "+f"(c[3])
        : "r"(a0), "r"(a1), "r"(a2), "r"(a3), "r"(b0), "r"(b1));
}
__device__ __forceinline__ void cp16(uint32_t s, const void* g) {
    asm volatile("cp.async.ca.shared.global [%0], [%1], 16;"
                 :: "r"(s), "l"(__cvta_generic_to_global(g)));
}
__device__ __forceinline__ void cp_commit() {
    asm volatile("cp.async.commit_group;");
}
template <int N>
__device__ __forceinline__ void cp_wait() {
    asm volatile("cp.async.wait_group %0;" :: "n"(N));
}

// split fp32x4 -> hi bf16x4 + lo bf16x4 (packed as uint2 each)
__device__ __forceinline__ void split8(uint2& hi, uint2& lo, float4 v) {
    __nv_bfloat162 h01 = __floats2bfloat162_rn(v.x, v.y);
    __nv_bfloat162 h23 = __floats2bfloat162_rn(v.z, v.w);
    float rx = v.x - __bfloat162float(h01.x);
    float ry = v.y - __bfloat162float(h01.y);
    float rz = v.z - __bfloat162float(h23.x);
    float rw = v.w - __bfloat162float(h23.y);
    hi = make_uint2(*(uint32_t*)&h01, *(uint32_t*)&h23);
    __nv_bfloat162 l01 = __floats2bfloat162_rn(rx, ry);
    __nv_bfloat162 l23 = __floats2bfloat162_rn(rz, rw);
    lo = make_uint2(*(uint32_t*)&l01, *(uint32_t*)&l23);
}
__device__ __forceinline__ void split2(uint32_t& hi, uint32_t& lo, float x, float y) {
    __nv_bfloat162 h = __floats2bfloat162_rn(x, y);
    float rx = x - __bfloat162float(h.x);
    float ry = y - __bfloat162float(h.y);
    hi = *(uint32_t*)&h;
    __nv_bfloat162 l = __floats2bfloat162_rn(rx, ry);
    lo = *(uint32_t*)&l;
}

// ===========================================================================
// Kernel 0: pre-split x and the 4 weight matrices (once).
// ===========================================================================
#define X_F4   (OUT_ELEMS / 4)
#define W_F4   (WELEMS / 4)
#define PREP_TOTAL (X_F4 + 4 * W_F4)

__global__ __launch_bounds__(256) void prep_kernel(
    const float* __restrict__ x,
    const float* __restrict__ qw, const float* __restrict__ kw,
    const float* __restrict__ vw, const float* __restrict__ ow)
{
    const size_t i = (size_t)blockIdx.x * 256 + threadIdx.x;
    if (i >= PREP_TOTAL) return;
    const float* src;
    __nv_bfloat16 *dh, *dl;
    size_t e;
    if (i < X_F4) {
        src = x; dh = g_xh; dl = g_xl; e = i;
    } else {
        const size_t wi = i - X_F4;
        const int wsel = (int)(wi / W_F4);
        e = wi % W_F4;
        src = (wsel == 0) ? qw : (wsel == 1) ? kw : (wsel == 2) ? vw : ow;
        dh = g_wh[wsel]; dl = g_wl[wsel];
    }
    float4 v = *(const float4*)(src + e * 4);
    uint2 h, l;
    split8(h, l, v);
    *(uint2*)(dh + e * 4) = h;
    *(uint2*)(dl + e * 4) = l;
}

// ===========================================================================
// Common bf16x3 HMMA GEMM core, cp.async 2-stage pipelined (R14-proven).
// MODE 0: head-scatter epilogue -> hi/lo bf16 [B,H,N,Hd] (qkv)
// MODE 1: plain fp32 [M,DIM] epilogue (o-proj)
// ===========================================================================
#define TSTR 40                           // bf16 per smem row (80B, conflict-free)
#define GT_ARR (128 * TSTR)               // 5120 elems per array
#define GT_STAGE (4 * GT_ARR)             // elems per stage (Ah,Al,Bh,Bl)
#define GT_SMEM_BYTES (2 * GT_STAGE * 2)  // 81920

template <int MODE>
__device__ __forceinline__ void tc_gemm_tile(
    const __nv_bfloat16* __restrict__ Agh, const __nv_bfloat16* __restrict__ Agl,
    const __nv_bfloat16* __restrict__ Wgh, const __nv_bfloat16* __restrict__ Wgl,
    const float* __restrict__ bias,
    float* __restrict__ dst, __nv_bfloat16* __restrict__ dsth,
    __nv_bfloat16* __restrict__ dstl,
    int m0, int n0)
{
    extern __shared__ __nv_bfloat16 gsm[];
    const int tid  = threadIdx.x;
    const int lane = tid & 31;
    const int wid  = tid >> 5;
    const int wm   = (wid >> 2) * 64;
    const int wn   = (wid & 3) * 32;
    const uint32_t sbase = smem_u32(gsm);

    auto issue = [&](int c, int s) {
        const uint32_t st = sbase + (uint32_t)s * (GT_STAGE * 2);
#pragma unroll
        for (int t = 0; t < 2; t++) {
            const int idx = tid + t * 256;           // 0..511
            const int row = idx >> 2;
            const int c8  = (idx & 3) * 8;
            const size_t ga = (size_t)(m0 + row) * DIM + c * 32 + c8;
            const size_t gb = (size_t)(n0 + row) * DIM + c * 32 + c8;
            const uint32_t so = (uint32_t)(row * TSTR + c8) * 2;
            cp16(st + 0 * GT_ARR * 2 + so, Agh + ga);
            cp16(st + 1 * GT_ARR * 2 + so, Agl + ga);
            cp16(st + 2 * GT_ARR * 2 + so, Wgh + gb);
            cp16(st + 3 * GT_ARR * 2 + so, Wgl + gb);
        }
        cp_commit();
    };

    float acc[4][4][4];
#pragma unroll
    for (int i = 0; i < 4; i++)
#pragma unroll
        for (int j = 0; j < 4; j++)
#pragma unroll
            for (int q = 0; q < 4; q++) acc[i][j][q] = 0.f;

    const uint32_t a_off = (wm + (lane & 15)) * (TSTR * 2) + (lane >> 4) * 16;
    const uint32_t b_row_base = wn + (lane & 7);
    const uint32_t b_off = ((lane >> 3) & 1) * 16;

    issue(0, 0);
    issue(1, 1);

    for (int c = 0; c < 36; c++) {
        const int s = c & 1;
        if (c + 1 < 36) cp_wait<1>(); else cp_wait<0>();
        __syncthreads();

        const uint32_t st = sbase + (uint32_t)s * (GT_STAGE * 2);
        const uint32_t ah = st, al = st + GT_ARR * 2;
        const uint32_t bh = st + 2 * GT_ARR * 2, bl = st + 3 * GT_ARR * 2;

#pragma unroll
        for (int ks = 0; ks < 2; ks++) {
            uint32_t Ah[4][4], Al[4][4], Bh[4][2], Bl[4][2];
#pragma unroll
            for (int mf = 0; mf < 4; mf++) {
                const uint32_t addr = a_off + mf * 16 * (TSTR * 2) + ks * 32;
                ldsm_x4(Ah[mf][0], Ah[mf][1], Ah[mf][2], Ah[mf][3], ah + addr);
                ldsm_x4(Al[mf][0], Al[mf][1], Al[mf][2], Al[mf][3], al + addr);
            }
#pragma unroll
            for (int nf = 0; nf < 4; nf++) {
                const uint32_t addr = (b_row_base + nf * 8) * (TSTR * 2) + ks * 32 + b_off;
                ldsm_x2(Bh[nf][0], Bh[nf][1], bh + addr);
                ldsm_x2(Bl[nf][0], Bl[nf][1], bl + addr);
            }
#pragma unroll
            for (int mf = 0; mf < 4; mf++)
#pragma unroll
                for (int nf = 0; nf < 4; nf++) {
                    mma16816(acc[mf][nf], Ah[mf][0], Ah[mf][1], Ah[mf][2], Ah[mf][3],
                             Bh[nf][0], Bh[nf][1]);
                    mma16816(acc[mf][nf], Al[mf][0], Al[mf][1], Al[mf][2], Al[mf][3],
                             Bh[nf][0], Bh[nf][1]);
                    mma16816(acc[mf][nf], Ah[mf][0], Ah[mf][1], Ah[mf][2], Ah[mf][3],
                             Bl[nf][0], Bl[nf][1]);
                }
        }
        __syncthreads();
        if (c + 2 < 36) issue(c + 2, s);
    }

    const int r_base = m0 + wm + (lane >> 2);
    const int c_base = n0 + wn + (lane & 3) * 2;
#pragma unroll
    for (int mf = 0; mf < 4; mf++) {
#pragma unroll
        for (int nf = 0; nf < 4; nf++) {
            const int col = c_base + nf * 8;
            const float bx = bias[col], by = bias[col + 1];
#pragma unroll
            for (int half = 0; half < 2; half++) {
                const int row = r_base + mf * 16 + half * 8;
                const float vx = acc[mf][nf][half * 2 + 0] + bx;
                const float vy = acc[mf][nf][half * 2 + 1] + by;
                if (MODE == 0) {
                    const int bb = row >> 10, n = row & 1023;
                    const int hdh = col / HD, hd = col % HD;
                    const size_t ga = ((size_t)(bb * NH + hdh) * SEQ + n) * HD + hd;
                    uint32_t hi, lo;
                    split2(hi, lo, vx, vy);
                    *(uint32_t*)(dsth + ga) = hi;
                    *(uint32_t*)(dstl + ga) = lo;
                } else {
                    float2 v; v.x = vx; v.y = vy;
                    *(float2*)(dst + (size_t)row * DIM + col) = v;
                }
            }
        }
    }
}

// Kernel 1: QKV projection -> pre-split bf16 head layout [B,H,N,Hd]
__global__ __launch_bounds__(256) void qkv_tc_kernel(
    const float* __restrict__ qb, const float* __restrict__ kb,
    const float* __restrict__ vb)
{
    const int proj = blockIdx.z;
    const float* bias = (proj == 0) ? qb : (proj == 1) ? kb : vb;
    __nv_bfloat16* dh = (proj == 0) ? g_qh : (proj == 1) ? g_kh : g_vh;
    __nv_bfloat16* dl = (proj == 0) ? g_ql : (proj == 1) ? g_kl : g_vl;
    tc_gemm_tile<0>(g_xh, g_xl, g_wh[proj], g_wl[proj], bias,
                    nullptr, dh, dl, blockIdx.y * 128, blockIdx.x * 128);
}

// Kernel 3: O projection (ctx pre-split by attention) -> fp32 out
__global__ __launch_bounds__(256) void oproj_tc_kernel(
    const float* __restrict__ ob, float* __restrict__ out)
{
    tc_gemm_tile<1>(g_ch, g_cl, g_wh[3], g_wl[3], ob,
                    out, nullptr, nullptr, blockIdx.y * 128, blockIdx.x * 128);
}

// ===========================================================================
// Kernel 2: FULLY FUSED attention, 512 threads, 32 q-rows per CTA.
//   Two 8-warp groups (group g = rows g*16..g*16+15) SHARE the K/V cp.async
//   double buffer -> halves the per-(b,h) K/V L2 re-read traffic vs 16-row
//   CTAs (the measured bottleneck).  Per-warp structure identical to the
//   R15-proven kernel: register S, no-max softmax, S-frag->A-frag PV,
//   8-way per-group ctx reduction.
// ===========================================================================
#define FS_THREADS 512
#define FS_KSTR 88
#define FS_TILE (128 * FS_KSTR)                  // per array (K or V tile)
#define FS_QOFF (4 * FS_TILE)                    // Q tiles after the 2 stages
#define FS_QROWS 32
#define FS_SMEM ((4 * FS_TILE + 2 * FS_QROWS * FS_KSTR) * 2)   // 101376 bytes
#define CTX_STR 76                               // fp32 ctx partial row stride

__global__ __launch_bounds__(FS_THREADS, 1) void fused_attn_kernel(
    float* __restrict__ probs)
{
    extern __shared__ __nv_bfloat16 ksm[];
    __shared__ float srow[16][16];       // [warp][row-in-group] partial sums
    const int tid  = threadIdx.x;
    const int lane = tid & 31;
    const int w    = tid >> 5;           // 0..15
    const int wg   = w >> 3;             // group 0/1 -> q rows wg*16..
    const int wl   = w & 7;              // warp within group
    const int q0   = blockIdx.x * FS_QROWS;
    const int bhx  = blockIdx.y;
    const int bb   = bhx >> 4, hh = bhx & 15;

    const __nv_bfloat16* Qgh = g_qh + ((size_t)bhx * SEQ + q0) * HD;
    const __nv_bfloat16* Qgl = g_ql + ((size_t)bhx * SEQ + q0) * HD;
    const __nv_bfloat16* Kgh = g_kh + (size_t)bhx * SEQ * HD;
    const __nv_bfloat16* Kgl = g_kl + (size_t)bhx * SEQ * HD;
    const __nv_bfloat16* Vgh = g_vh + (size_t)bhx * SEQ * HD;
    const __nv_bfloat16* Vgl = g_vl + (size_t)bhx * SEQ * HD;

    __nv_bfloat16* Qsh = ksm + FS_QOFF;
    __nv_bfloat16* Qsl = Qsh + FS_QROWS * FS_KSTR;

    // stage Q (pure copies) + zero Q pads [72,80)
    for (int idx = tid; idx < FS_QROWS * 9; idx += FS_THREADS) {
        const int row = idx / 9;
        const int c8  = (idx % 9) * 8;
        *(uint4*)(Qsh + row * FS_KSTR + c8) =
            *(const uint4*)(Qgh + (size_t)row * HD + c8);
        *(uint4*)(Qsl + row * FS_KSTR + c8) =
            *(const uint4*)(Qgl + (size_t)row * HD + c8);
    }
    for (int i = tid; i < 2 * FS_QROWS; i += FS_THREADS) {
        __nv_bfloat16* p = ((i & 1) ? Qsl : Qsh) + (i >> 1) * FS_KSTR + 72;
        *(uint2*)p = make_uint2(0, 0);
        *(uint2*)(p + 4) = make_uint2(0, 0);
    }
    // zero pads [72,80) of all 4 stage arrays
    for (int i = tid; i < 4 * 128; i += FS_THREADS) {
        __nv_bfloat16* p = ksm + (i >> 7) * FS_TILE + (i & 127) * FS_KSTR + 72;
        *(uint2*)p = make_uint2(0, 0);
        *(uint2*)(p + 4) = make_uint2(0, 0);
    }

    const uint32_t kbase = smem_u32(ksm);
    const uint32_t qh_base = smem_u32(Qsh);
    const uint32_t ql_base = smem_u32(Qsl);

    // stage a 128x72 tile (K or V) into stage s: pure cp.async copies
    auto issue = [&](const __nv_bfloat16* Gh, const __nv_bfloat16* Gl,
                     int tile, int s) {
        const uint32_t dh = kbase + (uint32_t)(2 * s) * (FS_TILE * 2);
        const uint32_t dl = dh + FS_TILE * 2;
        for (int idx = tid; idx < 128 * 9; idx += FS_THREADS) {
            const int row = idx / 9;
            const int c8  = (idx % 9) * 8;
            const size_t ga = (size_t)(tile * 128 + row) * HD + c8;
            const uint32_t so = (uint32_t)(row * FS_KSTR + c8) * 2;
            cp16(dh + so, Gh + ga);
            cp16(dl + so, Gl + ga);
        }
        cp_commit();
    };

    issue(Kgh, Kgl, 0, 0);
    issue(Kgh, Kgl, 1, 1);

    float acc[8][2][4];
#pragma unroll
    for (int kb = 0; kb < 8; kb++)
#pragma unroll
        for (int nf = 0; nf < 2; nf++)
#pragma unroll
            for (int q = 0; q < 4; q++) acc[kb][nf][q] = 0.f;

    const uint32_t q_off = (wg * 16 + (lane & 15)) * (FS_KSTR * 2) + (lane >> 4) * 16;
    const uint32_t b_row = wl * 16 + (lane & 7);
    const uint32_t b_off = ((lane >> 3) & 1) * 16;

    // ---- Phase 1: scores ----
#pragma unroll
    for (int kb = 0; kb < 8; kb++) {
        const int s = kb & 1;
        if (kb < 7) cp_wait<1>(); else cp_wait<0>();
        __syncthreads();
        const uint32_t kh = kbase + (uint32_t)(2 * s) * (FS_TILE * 2);
        const uint32_t kl = kh + FS_TILE * 2;
#pragma unroll
        for (int ks = 0; ks < 5; ks++) {
            uint32_t QA[4], QB[4], Bh[2][2], Bl[2][2];
            ldsm_x4(QA[0], QA[1], QA[2], QA[3], qh_base + q_off + ks * 32);
            ldsm_x4(QB[0], QB[1], QB[2], QB[3], ql_base + q_off + ks * 32);
#pragma unroll
            for (int nf = 0; nf < 2; nf++) {
                const uint32_t addr = (b_row + nf * 8) * (FS_KSTR * 2) + ks * 32 + b_off;
                ldsm_x2(Bh[nf][0], Bh[nf][1], kh + addr);
                ldsm_x2(Bl[nf][0], Bl[nf][1], kl + addr);
            }
#pragma unroll
            for (int nf = 0; nf < 2; nf++) {
                mma16816(acc[kb][nf], QA[0], QA[1], QA[2], QA[3], Bh[nf][0], Bh[nf][1]);
                mma16816(acc[kb][nf], QB[0], QB[1], QB[2], QB[3], Bh[nf][0], Bh[nf][1]);
                mma16816(acc[kb][nf], QA[0], QA[1], QA[2], QA[3], Bl[nf][0], Bl[nf][1]);
            }
        }
        __syncthreads();
        if (kb + 2 < 8) issue(Kgh, Kgl, kb + 2, s);
    }

    // start V loads immediately (overlap with softmax + probs writes)
    issue(Vgh, Vgl, 0, 0);
    issue(Vgh, Vgl, 1, 1);

    // ---- Phase 2: softmax (no max pass; exact shift-invariance) ----
    float rs0 = 0.f, rs1 = 0.f;
#pragma unroll
    for (int kb = 0; kb < 8; kb++)
#pragma unroll
        for (int nf = 0; nf < 2; nf++) {
            acc[kb][nf][0] = __expf(acc[kb][nf][0] * SCALE_F);
            acc[kb][nf][1] = __expf(acc[kb][nf][1] * SCALE_F);
            acc[kb][nf][2] = __expf(acc[kb][nf][2] * SCALE_F);
            acc[kb][nf][3] = __expf(acc[kb][nf][3] * SCALE_F);
            rs0 += acc[kb][nf][0] + acc[kb][nf][1];
            rs1 += acc[kb][nf][2] + acc[kb][nf][3];
        }
    rs0 += __shfl_xor_sync(~0u, rs0, 1);
    rs0 += __shfl_xor_sync(~0u, rs0, 2);
    rs1 += __shfl_xor_sync(~0u, rs1, 1);
    rs1 += __shfl_xor_sync(~0u, rs1, 2);

    const int r = lane >> 2;             // row within group (0..7; +8 pair)
    if ((lane & 3) == 0) {
        srow[w][r]     = rs0;
        srow[w][r + 8] = rs1;
    }
    __syncthreads();
    float t0 = 0.f, t1 = 0.f;
#pragma unroll
    for (int ww = 0; ww < 8; ww++) {
        t0 += srow[wg * 8 + ww][r];
        t1 += srow[wg * 8 + ww][r + 8];
    }
    const float inv0 = 1.f / t0;
    const float inv1 = 1.f / t1;

    // normalize S in regs; write probs fp32 (final output)
    const size_t rbase0 = (size_t)bhx * SEQ + q0 + wg * 16 + r;
    float* p0 = probs + rbase0 * SEQ;
    float* p1 = p0 + 8 * SEQ;
#pragma unroll
    for (int kb = 0; kb < 8; kb++)
#pragma unroll
        for (int nf = 0; nf < 2; nf++) {
            acc[kb][nf][0] *= inv0; acc[kb][nf][1] *= inv0;
            acc[kb][nf][2] *= inv1; acc[kb][nf][3] *= inv1;
            const int col = kb * 128 + wl * 16 + nf * 8 + (lane & 3) * 2;
            float2 v0, v1;
            v0.x = acc[kb][nf][0]; v0.y = acc[kb][nf][1];
            v1.x = acc[kb][nf][2]; v1.y = acc[kb][nf][3];
            *(float2*)(p0 + col) = v0;
            *(float2*)(p1 + col) = v1;
        }

    // ---- Phase 3: PV.  Each warp: its S frags (16 keys per tile) as A;
    //      V tile rows via ldmatrix.trans as B.  Partial ctx per warp. ----
    float cacc[9][4];
#pragma unroll
    for (int nf2 = 0; nf2 < 9; nf2++)
#pragma unroll
        for (int q = 0; q < 4; q++) cacc[nf2][q] = 0.f;

    const uint32_t v_row_addr = (uint32_t)(wl * 16 + (lane & 15)) * (FS_KSTR * 2);

#pragma unroll
    for (int vb = 0; vb < 8; vb++) {
        const int s = vb & 1;
        if (vb < 7) cp_wait<1>(); else cp_wait<0>();
        __syncthreads();
        const uint32_t vh = kbase + (uint32_t)(2 * s) * (FS_TILE * 2);
        const uint32_t vl = vh + FS_TILE * 2;

        // repack this warp's S C-frags -> A m16k16 frags (hi/lo bf16)
        uint32_t Ah[4], Al[4];
        split2(Ah[0], Al[0], acc[vb][0][0], acc[vb][0][1]);
        split2(Ah[1], Al[1], acc[vb][0][2], acc[vb][0][3]);
        split2(Ah[2], Al[2], acc[vb][1][0], acc[vb][1][1]);
        split2(Ah[3], Al[3], acc[vb][1][2], acc[vb][1][3]);

#pragma unroll
        for (int nf2 = 0; nf2 < 9; nf2++) {
            uint32_t Bh0, Bh1, Bl0, Bl1;
            const uint32_t addr = v_row_addr + nf2 * 8 * 2;
            ldsm_x2_trans(Bh0, Bh1, vh + addr);
            ldsm_x2_trans(Bl0, Bl1, vl + addr);
            mma16816(cacc[nf2], Ah[0], Ah[1], Ah[2], Ah[3], Bh0, Bh1);
            mma16816(cacc[nf2], Al[0], Al[1], Al[2], Al[3], Bh0, Bh1);
            mma16816(cacc[nf2], Ah[0], Ah[1], Ah[2], Ah[3], Bl0, Bl1);
        }
        __syncthreads();
        if (vb + 2 < 8) issue(Vgh, Vgl, vb + 2, s);
    }

    // ---- 8-way per-group ctx reduction through smem (reuse stage area) ----
    __syncthreads();                      // V stages dead; overlay sctx
    float* sctx = (float*)ksm;            // [16 warps][16 rows][CTX_STR]
    {
        const int cb = (lane & 3) * 2;
        float* base = sctx + w * (16 * CTX_STR);
#pragma unroll
        for (int nf2 = 0; nf2 < 9; nf2++) {
            const int col = nf2 * 8 + cb;
            *(float2*)(base + r * CTX_STR + col) =
                make_float2(cacc[nf2][0], cacc[nf2][1]);
            *(float2*)(base + (r + 8) * CTX_STR + col) =
                make_float2(cacc[nf2][2], cacc[nf2][3]);
        }
    }
    __syncthreads();

    // sum each group's 8 warp slots, split to hi/lo bf16, store ctx [B,N,D]
    for (int p = tid; p < FS_QROWS * 36; p += FS_THREADS) {
        const int row = p / 36;           // 0..31
        const int g   = row >> 4;
        const int rin = row & 15;
        const int c2  = (p % 36) * 2;
        float sx = 0.f, sy = 0.f;
#pragma unroll
        for (int ww = 0; ww < 8; ww++) {
            const float* b = sctx + (g * 8 + ww) * (16 * CTX_STR) + rin * CTX_STR + c2;
            sx += b[0];
            sy += b[1];
        }
        const size_t ga = ((size_t)bb * SEQ + q0 + row) * DIM + hh * HD + c2;
        uint32_t hi, lo;
        split2(hi, lo, sx, sy);
        *(uint32_t*)(g_ch + ga) = hi;
        *(uint32_t*)(g_cl + ga) = lo;
    }
}

// ---------------------------------------------------------------------------
extern "C" void kernel_launch(void* const* d_in, const int* in_sizes, int n_in,
                              void* d_out, int out_size)
{
    const float* x  = (const float*)d_in[0];
    const float* qw = (const float*)d_in[1];
    const float* qb = (const float*)d_in[2];
    const float* kw = (const float*)d_in[3];
    const float* kb = (const float*)d_in[4];
    const float* vw = (const float*)d_in[5];
    const float* vb = (const float*)d_in[6];
    const float* ow = (const float*)d_in[7];
    const float* ob = (const float*)d_in[8];

    float* out   = (float*)d_out;            // [B,N,D]
    float* probs = out + OUT_ELEMS;          // [B,H,N,N]

    cudaFuncSetAttribute(qkv_tc_kernel,
                         cudaFuncAttributeMaxDynamicSharedMemorySize, GT_SMEM_BYTES);
    cudaFuncSetAttribute(oproj_tc_kernel,
                         cudaFuncAttributeMaxDynamicSharedMemorySize, GT_SMEM_BYTES);
    cudaFuncSetAttribute(fused_attn_kernel,
                         cudaFuncAttributeMaxDynamicSharedMemorySize, FS_SMEM);

    prep_kernel<<<(PREP_TOTAL + 255) / 256, 256>>>(x, qw, kw, vw, ow);

    dim3 gq(DIM / 128, MTOT / 128, 3);       // (9, 64, 3)
    qkv_tc_kernel<<<gq, 256, GT_SMEM_BYTES>>>(qb, kb, vb);

    dim3 gs(SEQ / FS_QROWS, BD * NH);        // (32, 128)
    fused_attn_kernel<<<gs, FS_THREADS, FS_SMEM>>>(probs);

    dim3 go(DIM / 128, MTOT / 128);          // (9, 64)
    oproj_tc_kernel<<<go, 256, GT_SMEM_BYTES>>>(ob, out);
}

// round 17
// speedup vs baseline: 1.7920x; 1.0310x over previous
#include <cuda_runtime.h>
#include <cuda_bf16.h>
#include <cstdint>
#include <math.h>

// ---------------------------------------------------------------------------
// SiglipAttention: B=8, N=1024, D=1152, H=16, Hd=72
// Outputs (concatenated in d_out): out [B,N,D] fp32, attn_probs [B,H,N,N] fp32
// ---------------------------------------------------------------------------

#define BD   8
#define SEQ  1024
#define DIM  1152
#define NH   16
#define HD   72
#define MTOT (BD * SEQ)                 // 8192
#define QKV_ELEMS (BD * NH * SEQ * HD)  // 9437184
#define OUT_ELEMS (BD * SEQ * DIM)      // 9437184
#define WELEMS (DIM * DIM)              // 1327104
#define SCALE_F 0.117851130197757931f   // 72^-0.5

// Scratch (allocation-free rule: __device__ globals).  All MMA operands are
// PRE-SPLIT hi/lo bf16.  Q/K/V in [B,H,N,Hd]; ctx in [B,N,D].
__device__ __nv_bfloat16 g_xh[OUT_ELEMS],  g_xl[OUT_ELEMS];    // x
__device__ __nv_bfloat16 g_wh[4][WELEMS],  g_wl[4][WELEMS];    // q,k,v,o weights
__device__ __nv_bfloat16 g_qh[QKV_ELEMS],  g_ql[QKV_ELEMS];    // Q
__device__ __nv_bfloat16 g_kh[QKV_ELEMS],  g_kl[QKV_ELEMS];    // K
__device__ __nv_bfloat16 g_vh[QKV_ELEMS],  g_vl[QKV_ELEMS];    // V
__device__ __nv_bfloat16 g_ch[OUT_ELEMS],  g_cl[OUT_ELEMS];    // ctx

// ===========================================================================
// HMMA + cp.async helpers (sm_80+ paths; tcgen05 unavailable on sm_103 base)
// ===========================================================================
__device__ __forceinline__ uint32_t smem_u32(const void* p) {
    uint32_t a;
    asm("{ .reg .u64 t; cvta.to.shared.u64 t, %1; cvt.u32.u64 %0, t; }"
        : "=r"(a) : "l"(p));
    return a;
}
__device__ __forceinline__ void ldsm_x4(uint32_t& r0, uint32_t& r1,
                                        uint32_t& r2, uint32_t& r3, uint32_t a) {
    asm volatile("ldmatrix.sync.aligned.m8n8.x4.shared.b16 {%0,%1,%2,%3}, [%4];"
                 : "=r"(r0), "=r"(r1), "=r"(r2), "=r"(r3) : "r"(a));
}
__device__ __forceinline__ void ldsm_x2(uint32_t& r0, uint32_t& r1, uint32_t a) {
    asm volatile("ldmatrix.sync.aligned.m8n8.x2.shared.b16 {%0,%1}, [%2];"
                 : "=r"(r0), "=r"(r1) : "r"(a));
}
__device__ __forceinline__ void ldsm_x2_trans(uint32_t& r0, uint32_t& r1, uint32_t a) {
    asm volatile("ldmatrix.sync.aligned.m8n8.x2.trans.shared.b16 {%0,%1}, [%2];"
                 : "=r"(r0), "=r"(r1) : "r"(a));
}
__device__ __forceinline__ void mma16816(float* c,
                                         uint32_t a0, uint32_t a1, uint32_t a2, uint32_t a3,
                                         uint32_t b0, uint32_t b1) {
    asm volatile(
        "mma.sync.aligned.m16n8k16.row.col.f32.bf16.bf16.f32 "
        "{%0,%1,%2,%3}, {%4,%5,%6,%7}, {%8,%9}, {%0,%1,%2,%3};"
        : "+f"(c[0]), "+f"(c[1]), "+f"(c[2]), "+f"(c[3])
        : "r"(a0), "r"(a1), "r"(a2), "r"(a3), "r"(b0), "r"(b1));
}
__device__ __forceinline__ void cp16(uint32_t s, const void* g) {
    asm volatile("cp.async.ca.shared.global [%0], [%1], 16;"
                 :: "r"(s), "l"(__cvta_generic_to_global(g)));
}
__device__ __forceinline__ void cp_commit() {
    asm volatile("cp.async.commit_group;");
}
template <int N>
__device__ __forceinline__ void cp_wait() {
    asm volatile("cp.async.wait_group %0;" :: "n"(N));
}

// split fp32x4 -> hi bf16x4 + lo bf16x4 (packed as uint2 each)
__device__ __forceinline__ void split8(uint2& hi, uint2& lo, float4 v) {
    __nv_bfloat162 h01 = __floats2bfloat162_rn(v.x, v.y);
    __nv_bfloat162 h23 = __floats2bfloat162_rn(v.z, v.w);
    float rx = v.x - __bfloat162float(h01.x);
    float ry = v.y - __bfloat162float(h01.y);
    float rz = v.z - __bfloat162float(h23.x);
    float rw = v.w - __bfloat162float(h23.y);
    hi = make_uint2(*(uint32_t*)&h01, *(uint32_t*)&h23);
    __nv_bfloat162 l01 = __floats2bfloat162_rn(rx, ry);
    __nv_bfloat162 l23 = __floats2bfloat162_rn(rz, rw);
    lo = make_uint2(*(uint32_t*)&l01, *(uint32_t*)&l23);
}
__device__ __forceinline__ void split2(uint32_t& hi, uint32_t& lo, float x, float y) {
    __nv_bfloat162 h = __floats2bfloat162_rn(x, y);
    float rx = x - __bfloat162float(h.x);
    float ry = y - __bfloat162float(h.y);
    hi = *(uint32_t*)&h;
    __nv_bfloat162 l = __floats2bfloat162_rn(rx, ry);
    lo = *(uint32_t*)&l;
}

// ===========================================================================
// Kernel 0: pre-split x and the 4 weight matrices (once).
// ===========================================================================
#define X_F4   (OUT_ELEMS / 4)
#define W_F4   (WELEMS / 4)
#define PREP_TOTAL (X_F4 + 4 * W_F4)

__global__ __launch_bounds__(256) void prep_kernel(
    const float* __restrict__ x,
    const float* __restrict__ qw, const float* __restrict__ kw,
    const float* __restrict__ vw, const float* __restrict__ ow)
{
    const size_t i = (size_t)blockIdx.x * 256 + threadIdx.x;
    if (i >= PREP_TOTAL) return;
    const float* src;
    __nv_bfloat16 *dh, *dl;
    size_t e;
    if (i < X_F4) {
        src = x; dh = g_xh; dl = g_xl; e = i;
    } else {
        const size_t wi = i - X_F4;
        const int wsel = (int)(wi / W_F4);
        e = wi % W_F4;
        src = (wsel == 0) ? qw : (wsel == 1) ? kw : (wsel == 2) ? vw : ow;
        dh = g_wh[wsel]; dl = g_wl[wsel];
    }
    float4 v = *(const float4*)(src + e * 4);
    uint2 h, l;
    split8(h, l, v);
    *(uint2*)(dh + e * 4) = h;
    *(uint2*)(dl + e * 4) = l;
}

// ===========================================================================
// Common bf16x3 HMMA GEMM core, cp.async 2-stage pipelined (R14-proven).
// MODE 0: head-scatter epilogue -> hi/lo bf16 [B,H,N,Hd] (qkv)
// MODE 1: plain fp32 [M,DIM] epilogue (o-proj)
// ===========================================================================
#define TSTR 40                           // bf16 per smem row (80B, conflict-free)
#define GT_ARR (128 * TSTR)               // 5120 elems per array
#define GT_STAGE (4 * GT_ARR)             // elems per stage (Ah,Al,Bh,Bl)
#define GT_SMEM_BYTES (2 * GT_STAGE * 2)  // 81920

template <int MODE>
__device__ __forceinline__ void tc_gemm_tile(
    const __nv_bfloat16* __restrict__ Agh, const __nv_bfloat16* __restrict__ Agl,
    const __nv_bfloat16* __restrict__ Wgh, const __nv_bfloat16* __restrict__ Wgl,
    const float* __restrict__ bias,
    float* __restrict__ dst, __nv_bfloat16* __restrict__ dsth,
    __nv_bfloat16* __restrict__ dstl,
    int m0, int n0)
{
    extern __shared__ __nv_bfloat16 gsm[];
    const int tid  = threadIdx.x;
    const int lane = tid & 31;
    const int wid  = tid >> 5;
    const int wm   = (wid >> 2) * 64;
    const int wn   = (wid & 3) * 32;
    const uint32_t sbase = smem_u32(gsm);

    auto issue = [&](int c, int s) {
        const uint32_t st = sbase + (uint32_t)s * (GT_STAGE * 2);
#pragma unroll
        for (int t = 0; t < 2; t++) {
            const int idx = tid + t * 256;           // 0..511
            const int row = idx >> 2;
            const int c8  = (idx & 3) * 8;
            const size_t ga = (size_t)(m0 + row) * DIM + c * 32 + c8;
            const size_t gb = (size_t)(n0 + row) * DIM + c * 32 + c8;
            const uint32_t so = (uint32_t)(row * TSTR + c8) * 2;
            cp16(st + 0 * GT_ARR * 2 + so, Agh + ga);
            cp16(st + 1 * GT_ARR * 2 + so, Agl + ga);
            cp16(st + 2 * GT_ARR * 2 + so, Wgh + gb);
            cp16(st + 3 * GT_ARR * 2 + so, Wgl + gb);
        }
        cp_commit();
    };

    float acc[4][4][4];
#pragma unroll
    for (int i = 0; i < 4; i++)
#pragma unroll
        for (int j = 0; j < 4; j++)
#pragma unroll
            for (int q = 0; q < 4; q++) acc[i][j][q] = 0.f;

    const uint32_t a_off = (wm + (lane & 15)) * (TSTR * 2) + (lane >> 4) * 16;
    const uint32_t b_row_base = wn + (lane & 7);
    const uint32_t b_off = ((lane >> 3) & 1) * 16;

    issue(0, 0);
    issue(1, 1);

    for (int c = 0; c < 36; c++) {
        const int s = c & 1;
        if (c + 1 < 36) cp_wait<1>(); else cp_wait<0>();
        __syncthreads();

        const uint32_t st = sbase + (uint32_t)s * (GT_STAGE * 2);
        const uint32_t ah = st, al = st + GT_ARR * 2;
        const uint32_t bh = st + 2 * GT_ARR * 2, bl = st + 3 * GT_ARR * 2;

#pragma unroll
        for (int ks = 0; ks < 2; ks++) {
            uint32_t Ah[4][4], Al[4][4], Bh[4][2], Bl[4][2];
#pragma unroll
            for (int mf = 0; mf < 4; mf++) {
                const uint32_t addr = a_off + mf * 16 * (TSTR * 2) + ks * 32;
                ldsm_x4(Ah[mf][0], Ah[mf][1], Ah[mf][2], Ah[mf][3], ah + addr);
                ldsm_x4(Al[mf][0], Al[mf][1], Al[mf][2], Al[mf][3], al + addr);
            }
#pragma unroll
            for (int nf = 0; nf < 4; nf++) {
                const uint32_t addr = (b_row_base + nf * 8) * (TSTR * 2) + ks * 32 + b_off;
                ldsm_x2(Bh[nf][0], Bh[nf][1], bh + addr);
                ldsm_x2(Bl[nf][0], Bl[nf][1], bl + addr);
            }
#pragma unroll
            for (int mf = 0; mf < 4; mf++)
#pragma unroll
                for (int nf = 0; nf < 4; nf++) {
                    mma16816(acc[mf][nf], Ah[mf][0], Ah[mf][1], Ah[mf][2], Ah[mf][3],
                             Bh[nf][0], Bh[nf][1]);
                    mma16816(acc[mf][nf], Al[mf][0], Al[mf][1], Al[mf][2], Al[mf][3],
                             Bh[nf][0], Bh[nf][1]);
                    mma16816(acc[mf][nf], Ah[mf][0], Ah[mf][1], Ah[mf][2], Ah[mf][3],
                             Bl[nf][0], Bl[nf][1]);
                }
        }
        __syncthreads();
        if (c + 2 < 36) issue(c + 2, s);
    }

    const int r_base = m0 + wm + (lane >> 2);
    const int c_base = n0 + wn + (lane & 3) * 2;
#pragma unroll
    for (int mf = 0; mf < 4; mf++) {
#pragma unroll
        for (int nf = 0; nf < 4; nf++) {
            const int col = c_base + nf * 8;
            const float bx = bias[col], by = bias[col + 1];
#pragma unroll
            for (int half = 0; half < 2; half++) {
                const int row = r_base + mf * 16 + half * 8;
                const float vx = acc[mf][nf][half * 2 + 0] + bx;
                const float vy = acc[mf][nf][half * 2 + 1] + by;
                if (MODE == 0) {
                    const int bb = row >> 10, n = row & 1023;
                    const int hdh = col / HD, hd = col % HD;
                    const size_t ga = ((size_t)(bb * NH + hdh) * SEQ + n) * HD + hd;
                    uint32_t hi, lo;
                    split2(hi, lo, vx, vy);
                    *(uint32_t*)(dsth + ga) = hi;
                    *(uint32_t*)(dstl + ga) = lo;
                } else {
                    float2 v; v.x = vx; v.y = vy;
                    *(float2*)(dst + (size_t)row * DIM + col) = v;
                }
            }
        }
    }
}

// Kernel 1: QKV projection -> pre-split bf16 head layout [B,H,N,Hd]
__global__ __launch_bounds__(256) void qkv_tc_kernel(
    const float* __restrict__ qb, const float* __restrict__ kb,
    const float* __restrict__ vb)
{
    const int proj = blockIdx.z;
    const float* bias = (proj == 0) ? qb : (proj == 1) ? kb : vb;
    __nv_bfloat16* dh = (proj == 0) ? g_qh : (proj == 1) ? g_kh : g_vh;
    __nv_bfloat16* dl = (proj == 0) ? g_ql : (proj == 1) ? g_kl : g_vl;
    tc_gemm_tile<0>(g_xh, g_xl, g_wh[proj], g_wl[proj], bias,
                    nullptr, dh, dl, blockIdx.y * 128, blockIdx.x * 128);
}

// Kernel 3: O projection (ctx pre-split by attention) -> fp32 out
__global__ __launch_bounds__(256) void oproj_tc_kernel(
    const float* __restrict__ ob, float* __restrict__ out)
{
    tc_gemm_tile<1>(g_ch, g_cl, g_wh[3], g_wl[3], ob,
                    out, nullptr, nullptr, blockIdx.y * 128, blockIdx.x * 128);
}

// ===========================================================================
// Kernel 2: FULLY FUSED attention, 512 threads, 32 q-rows per CTA.
//   UNIFIED 16-tile (K0..K7,V0..V7) 3-STAGE cp.async pipeline:
//   one __syncthreads per tile (wait -> sync -> issue(t+2) -> compute),
//   V prefetch naturally overlaps the softmax phase.  Per-warp math
//   identical to the R16-proven kernel (register S, no-max softmax,
//   S-frag->A-frag PV, per-group 8-way ctx reduction).
// ===========================================================================
#define FS_THREADS 512
#define FS_KSTR 88
#define FS_TILE (128 * FS_KSTR)                  // elems per array (one tile)
#define FS_QOFF (6 * FS_TILE)                    // Q after the 3 stages
#define FS_QROWS 32
#define FS_SMEM ((6 * FS_TILE + 2 * FS_QROWS * FS_KSTR) * 2)   // 146432 bytes
#define CTX_STR 76                               // fp32 ctx partial row stride

__global__ __launch_bounds__(FS_THREADS, 1) void fused_attn_kernel(
    float* __restrict__ probs)
{
    extern __shared__ __nv_bfloat16 ksm[];
    __shared__ float srow[16][16];       // [warp][row-in-group] partial sums
    const int tid  = threadIdx.x;
    const int lane = tid & 31;
    const int w    = tid >> 5;           // 0..15
    const int wg   = w >> 3;             // group 0/1 -> q rows wg*16..
    const int wl   = w & 7;              // warp within group
    const int q0   = blockIdx.x * FS_QROWS;
    const int bhx  = blockIdx.y;
    const int bb   = bhx >> 4, hh = bhx & 15;

    const __nv_bfloat16* Qgh = g_qh + ((size_t)bhx * SEQ + q0) * HD;
    const __nv_bfloat16* Qgl = g_ql + ((size_t)bhx * SEQ + q0) * HD;
    const __nv_bfloat16* Kgh = g_kh + (size_t)bhx * SEQ * HD;
    const __nv_bfloat16* Kgl = g_kl + (size_t)bhx * SEQ * HD;
    const __nv_bfloat16* Vgh = g_vh + (size_t)bhx * SEQ * HD;
    const __nv_bfloat16* Vgl = g_vl + (size_t)bhx * SEQ * HD;

    __nv_bfloat16* Qsh = ksm + FS_QOFF;
    __nv_bfloat16* Qsl = Qsh + FS_QROWS * FS_KSTR;

    // stage Q (pure copies) + zero Q pads [72,80)
    for (int idx = tid; idx < FS_QROWS * 9; idx += FS_THREADS) {
        const int row = idx / 9;
        const int c8  = (idx % 9) * 8;
        *(uint4*)(Qsh + row * FS_KSTR + c8) =
            *(const uint4*)(Qgh + (size_t)row * HD + c8);
        *(uint4*)(Qsl + row * FS_KSTR + c8) =
            *(const uint4*)(Qgl + (size_t)row * HD + c8);
    }
    for (int i = tid; i < 2 * FS_QROWS; i += FS_THREADS) {
        __nv_bfloat16* p = ((i & 1) ? Qsl : Qsh) + (i >> 1) * FS_KSTR + 72;
        *(uint2*)p = make_uint2(0, 0);
        *(uint2*)(p + 4) = make_uint2(0, 0);
    }
    // zero pads [72,80) of all 6 stage arrays
    for (int i = tid; i < 6 * 128; i += FS_THREADS) {
        __nv_bfloat16* p = ksm + (i >> 7) * FS_TILE + (i & 127) * FS_KSTR + 72;
        *(uint2*)p = make_uint2(0, 0);
        *(uint2*)(p + 4) = make_uint2(0, 0);
    }

    const uint32_t kbase = smem_u32(ksm);
    const uint32_t qh_base = smem_u32(Qsh);
    const uint32_t ql_base = smem_u32(Qsl);

    // stage tile t (t<8: K tile t, else V tile t-8) into stage t%3
    auto issue = [&](int t) {
        const __nv_bfloat16* Gh = (t < 8) ? Kgh : Vgh;
        const __nv_bfloat16* Gl = (t < 8) ? Kgl : Vgl;
        const int tile = t & 7;
        const uint32_t dh = kbase + (uint32_t)(2 * (t % 3)) * (FS_TILE * 2);
        const uint32_t dl = dh + FS_TILE * 2;
        for (int idx = tid; idx < 128 * 9; idx += FS_THREADS) {
            const int row = idx / 9;
            const int c8  = (idx % 9) * 8;
            const size_t ga = (size_t)(tile * 128 + row) * HD + c8;
            const uint32_t so = (uint32_t)(row * FS_KSTR + c8) * 2;
            cp16(dh + so, Gh + ga);
            cp16(dl + so, Gl + ga);
        }
        cp_commit();
    };

    issue(0);
    issue(1);

    float acc[8][2][4];
#pragma unroll
    for (int kb = 0; kb < 8; kb++)
#pragma unroll
        for (int nf = 0; nf < 2; nf++)
#pragma unroll
            for (int q = 0; q < 4; q++) acc[kb][nf][q] = 0.f;

    const uint32_t q_off = (wg * 16 + (lane & 15)) * (FS_KSTR * 2) + (lane >> 4) * 16;
    const uint32_t b_row = wl * 16 + (lane & 7);
    const uint32_t b_off = ((lane >> 3) & 1) * 16;

    // ---- Phase 1: scores (tiles 0..7) ----
#pragma unroll
    for (int kb = 0; kb < 8; kb++) {
        cp_wait<1>();
        __syncthreads();            // everyone done with tile kb-1's stage
        issue(kb + 2);              // K for kb<6, V0/V1 for kb=6,7
        const uint32_t kh = kbase + (uint32_t)(2 * (kb % 3)) * (FS_TILE * 2);
        const uint32_t kl = kh + FS_TILE * 2;
#pragma unroll
        for (int ks = 0; ks < 5; ks++) {
            uint32_t QA[4], QB[4], Bh[2][2], Bl[2][2];
            ldsm_x4(QA[0], QA[1], QA[2], QA[3], qh_base + q_off + ks * 32);
            ldsm_x4(QB[0], QB[1], QB[2], QB[3], ql_base + q_off + ks * 32);
#pragma unroll
            for (int nf = 0; nf < 2; nf++) {
                const uint32_t addr = (b_row + nf * 8) * (FS_KSTR * 2) + ks * 32 + b_off;
                ldsm_x2(Bh[nf][0], Bh[nf][1], kh + addr);
                ldsm_x2(Bl[nf][0], Bl[nf][1], kl + addr);
            }
#pragma unroll
            for (int nf = 0; nf < 2; nf++) {
                mma16816(acc[kb][nf], QA[0], QA[1], QA[2], QA[3], Bh[nf][0], Bh[nf][1]);
                mma16816(acc[kb][nf], QB[0], QB[1], QB[2], QB[3], Bh[nf][0], Bh[nf][1]);
                mma16816(acc[kb][nf], QA[0], QA[1], QA[2], QA[3], Bl[nf][0], Bl[nf][1]);
            }
        }
    }

    // ---- Phase 2: softmax (V0/V1 cp.async in flight underneath) ----
    float rs0 = 0.f, rs1 = 0.f;
#pragma unroll
    for (int kb = 0; kb < 8; kb++)
#pragma unroll
        for (int nf = 0; nf < 2; nf++) {
            acc[kb][nf][0] = __expf(acc[kb][nf][0] * SCALE_F);
            acc[kb][nf][1] = __expf(acc[kb][nf][1] * SCALE_F);
            acc[kb][nf][2] = __expf(acc[kb][nf][2] * SCALE_F);
            acc[kb][nf][3] = __expf(acc[kb][nf][3] * SCALE_F);
            rs0 += acc[kb][nf][0] + acc[kb][nf][1];
            rs1 += acc[kb][nf][2] + acc[kb][nf][3];
        }
    rs0 += __shfl_xor_sync(~0u, rs0, 1);
    rs0 += __shfl_xor_sync(~0u, rs0, 2);
    rs1 += __shfl_xor_sync(~0u, rs1, 1);
    rs1 += __shfl_xor_sync(~0u, rs1, 2);

    const int r = lane >> 2;             // row within group (0..7; +8 pair)
    if ((lane & 3) == 0) {
        srow[w][r]     = rs0;
        srow[w][r + 8] = rs1;
    }
    __syncthreads();
    float t0 = 0.f, t1 = 0.f;
#pragma unroll
    for (int ww = 0; ww < 8; ww++) {
        t0 += srow[wg * 8 + ww][r];
        t1 += srow[wg * 8 + ww][r + 8];
    }
    const float inv0 = 1.f / t0;
    const float inv1 = 1.f / t1;

    // normalize S in regs; write probs fp32 (final output)
    const size_t rbase0 = (size_t)bhx * SEQ + q0 + wg * 16 + r;
    float* p0 = probs + rbase0 * SEQ;
    float* p1 = p0 + 8 * SEQ;
#pragma unroll
    for (int kb = 0; kb < 8; kb++)
#pragma unroll
        for (int nf = 0; nf < 2; nf++) {
            acc[kb][nf][0] *= inv0; acc[kb][nf][1] *= inv0;
            acc[kb][nf][2] *= inv1; acc[kb][nf][3] *= inv1;
            const int col = kb * 128 + wl * 16 + nf * 8 + (lane & 3) * 2;
            float2 v0, v1;
            v0.x = acc[kb][nf][0]; v0.y = acc[kb][nf][1];
            v1.x = acc[kb][nf][2]; v1.y = acc[kb][nf][3];
            *(float2*)(p0 + col) = v0;
            *(float2*)(p1 + col) = v1;
        }

    // ---- Phase 3: PV (tiles 8..15 in the same pipeline rotation) ----
    float cacc[9][4];
#pragma unroll
    for (int nf2 = 0; nf2 < 9; nf2++)
#pragma unroll
        for (int q = 0; q < 4; q++) cacc[nf2][q] = 0.f;

    const uint32_t v_row_addr = (uint32_t)(wl * 16 + (lane & 15)) * (FS_KSTR * 2);

#pragma unroll
    for (int vb = 0; vb < 8; vb++) {
        const int t = 8 + vb;
        if (t < 15) cp_wait<1>(); else cp_wait<0>();
        __syncthreads();            // everyone done with tile t-1's stage
        if (t + 2 < 16) issue(t + 2);
        const uint32_t vh = kbase + (uint32_t)(2 * (t % 3)) * (FS_TILE * 2);
        const uint32_t vl = vh + FS_TILE * 2;

        // repack this warp's S C-frags -> A m16k16 frags (hi/lo bf16)
        uint32_t Ah[4], Al[4];
        split2(Ah[0], Al[0], acc[vb][0][0], acc[vb][0][1]);
        split2(Ah[1], Al[1], acc[vb][0][2], acc[vb][0][3]);
        split2(Ah[2], Al[2], acc[vb][1][0], acc[vb][1][1]);
        split2(Ah[3], Al[3], acc[vb][1][2], acc[vb][1][3]);

#pragma unroll
        for (int nf2 = 0; nf2 < 9; nf2++) {
            uint32_t Bh0, Bh1, Bl0, Bl1;
            const uint32_t addr = v_row_addr + nf2 * 8 * 2;
            ldsm_x2_trans(Bh0, Bh1, vh + addr);
            ldsm_x2_trans(Bl0, Bl1, vl + addr);
            mma16816(cacc[nf2], Ah[0], Ah[1], Ah[2], Ah[3], Bh0, Bh1);
            mma16816(cacc[nf2], Al[0], Al[1], Al[2], Al[3], Bh0, Bh1);
            mma16816(cacc[nf2], Ah[0], Ah[1], Ah[2], Ah[3], Bl0, Bl1);
        }
    }

    // ---- 8-way per-group ctx reduction through smem (reuse stage area) ----
    __syncthreads();                      // stage tiles dead; overlay sctx
    float* sctx = (float*)ksm;            // [16 warps][16 rows][CTX_STR]
    {
        const int cb = (lane & 3) * 2;
        float* base = sctx + w * (16 * CTX_STR);
#pragma unroll
        for (int nf2 = 0; nf2 < 9; nf2++) {
            const int col = nf2 * 8 + cb;
            *(float2*)(base + r * CTX_STR + col) =
                make_float2(cacc[nf2][0], cacc[nf2][1]);
            *(float2*)(base + (r + 8) * CTX_STR + col) =
                make_float2(cacc[nf2][2], cacc[nf2][3]);
        }
    }
    __syncthreads();

    // sum each group's 8 warp slots, split to hi/lo bf16, store ctx [B,N,D]
    for (int p = tid; p < FS_QROWS * 36; p += FS_THREADS) {
        const int row = p / 36;           // 0..31
        const int g   = row >> 4;
        const int rin = row & 15;
        const int c2  = (p % 36) * 2;
        float sx = 0.f, sy = 0.f;
#pragma unroll
        for (int ww = 0; ww < 8; ww++) {
            const float* b = sctx + (g * 8 + ww) * (16 * CTX_STR) + rin * CTX_STR + c2;
            sx += b[0];
            sy += b[1];
        }
        const size_t ga = ((size_t)bb * SEQ + q0 + row) * DIM + hh * HD + c2;
        uint32_t hi, lo;
        split2(hi, lo, sx, sy);
        *(uint32_t*)(g_ch + ga) = hi;
        *(uint32_t*)(g_cl + ga) = lo;
    }
}

// ---------------------------------------------------------------------------
extern "C" void kernel_launch(void* const* d_in, const int* in_sizes, int n_in,
                              void* d_out, int out_size)
{
    const float* x  = (const float*)d_in[0];
    const float* qw = (const float*)d_in[1];
    const float* qb = (const float*)d_in[2];
    const float* kw = (const float*)d_in[3];
    const float* kb = (const float*)d_in[4];
    const float* vw = (const float*)d_in[5];
    const float* vb = (const float*)d_in[6];
    const float* ow = (const float*)d_in[7];
    const float* ob = (const float*)d_in[8];

    float* out   = (float*)d_out;            // [B,N,D]
    float* probs = out + OUT_ELEMS;          // [B,H,N,N]

    cudaFuncSetAttribute(qkv_tc_kernel,
                         cudaFuncAttributeMaxDynamicSharedMemorySize, GT_SMEM_BYTES);
    cudaFuncSetAttribute(oproj_tc_kernel,
                         cudaFuncAttributeMaxDynamicSharedMemorySize, GT_SMEM_BYTES);
    cudaFuncSetAttribute(fused_attn_kernel,
                         cudaFuncAttributeMaxDynamicSharedMemorySize, FS_SMEM);

    prep_kernel<<<(PREP_TOTAL + 255) / 256, 256>>>(x, qw, kw, vw, ow);

    dim3 gq(DIM / 128, MTOT / 128, 3);       // (9, 64, 3)
    qkv_tc_kernel<<<gq, 256, GT_SMEM_BYTES>>>(qb, kb, vb);

    dim3 gs(SEQ / FS_QROWS, BD * NH);        // (32, 128)
    fused_attn_kernel<<<gs, FS_THREADS, FS_SMEM>>>(probs);

    dim3 go(DIM / 128, MTOT / 128);          // (9, 64)
    oproj_tc_kernel<<<go, 256, GT_SMEM_BYTES>>>(ob, out);
}